// round 1
// baseline (speedup 1.0000x reference)
#include <cuda_runtime.h>
#include <math.h>

#define D_MODEL 512
#define N_HEADS 8
#define D_KK    64
#define D_FF    2048
#define T_SEQ   2048
#define B_BATCH 2
#define BT      (B_BATCH * T_SEQ)    /* 4096 rows */
#define BH      (B_BATCH * N_HEADS)  /* 16 batched heads */

#define OUT_ELEMS  ((size_t)BT * D_MODEL)                 /* 2,097,152 */
#define ATTN_ELEMS ((size_t)BH * T_SEQ * T_SEQ)           /* 67,108,864 */

enum { EPI_NONE = 0, EPI_RELU = 1, EPI_QKV = 2 };

/* ---------------- scratch (device globals: no allocation allowed) -------- */
__device__ float g_q[BH * T_SEQ * D_KK];
__device__ float g_k[BH * T_SEQ * D_KK];
__device__ float g_v[BH * T_SEQ * D_KK];
__device__ float g_ctx[BT * D_MODEL];
__device__ float g_tmp[BT * D_MODEL];      /* attn_out, then ffn2 */
__device__ float g_h[BT * D_MODEL];
__device__ float g_ffn1[BT * D_FF];
__device__ float g_attn_scratch[BH * (size_t)T_SEQ * T_SEQ]; /* fallback if attn not in d_out */

/* ---------------- small reduction helpers -------------------------------- */
__device__ __forceinline__ float warp_sum(float v) {
    #pragma unroll
    for (int o = 16; o > 0; o >>= 1) v += __shfl_xor_sync(0xffffffffu, v, o);
    return v;
}
__device__ __forceinline__ float warp_max(float v) {
    #pragma unroll
    for (int o = 16; o > 0; o >>= 1) v = fmaxf(v, __shfl_xor_sync(0xffffffffu, v, o));
    return v;
}

/* ---------------- generic 128x128x8 SGEMM: C = A@W + bias ----------------
 * A: [M,K] row-major, W: [K,N] row-major, bias: [N]
 * mode EPI_QKV scatters C[m, n] -> [b, h, t, d] layout for attention.
 */
__global__ __launch_bounds__(256) void gemm_kernel(
    const float* __restrict__ A, const float* __restrict__ W,
    const float* __restrict__ bias, float* __restrict__ C,
    int M, int N, int K, int mode)
{
    __shared__ float As[8][128];
    __shared__ float Ws[8][128];

    const int tid = threadIdx.x;
    const int tx = tid & 15, ty = tid >> 4;
    const int bm = blockIdx.y * 128, bn = blockIdx.x * 128;

    const int arow = tid >> 1, acol = (tid & 1) * 4;   /* A tile 128x8 */
    const int wrow = tid >> 5, wcol = (tid & 31) * 4;  /* W tile 8x128 */

    float acc[8][8];
    #pragma unroll
    for (int i = 0; i < 8; i++)
        #pragma unroll
        for (int j = 0; j < 8; j++) acc[i][j] = 0.0f;

    const float* Aptr = A + (size_t)(bm + arow) * K + acol;
    const float* Wptr = W + (size_t)wrow * N + bn + wcol;

    for (int k0 = 0; k0 < K; k0 += 8) {
        float4 av = *(const float4*)(Aptr + k0);
        As[acol + 0][arow] = av.x;
        As[acol + 1][arow] = av.y;
        As[acol + 2][arow] = av.z;
        As[acol + 3][arow] = av.w;
        *(float4*)&Ws[wrow][wcol] = *(const float4*)(Wptr + (size_t)k0 * N);
        __syncthreads();

        #pragma unroll
        for (int k = 0; k < 8; k++) {
            float4 a0 = *(const float4*)&As[k][ty * 4];
            float4 a1 = *(const float4*)&As[k][64 + ty * 4];
            float4 b0 = *(const float4*)&Ws[k][tx * 4];
            float4 b1 = *(const float4*)&Ws[k][64 + tx * 4];
            float a[8] = {a0.x, a0.y, a0.z, a0.w, a1.x, a1.y, a1.z, a1.w};
            float b[8] = {b0.x, b0.y, b0.z, b0.w, b1.x, b1.y, b1.z, b1.w};
            #pragma unroll
            for (int i = 0; i < 8; i++)
                #pragma unroll
                for (int j = 0; j < 8; j++)
                    acc[i][j] = fmaf(a[i], b[j], acc[i][j]);
        }
        __syncthreads();
    }

    #pragma unroll
    for (int i = 0; i < 8; i++) {
        int m = bm + (i >> 2) * 64 + ty * 4 + (i & 3);
        #pragma unroll
        for (int j = 0; j < 8; j++) {
            int n = bn + (j >> 2) * 64 + tx * 4 + (j & 3);
            float vv = acc[i][j] + bias[n];
            if (mode == EPI_RELU) vv = fmaxf(vv, 0.0f);
            if (mode == EPI_QKV) {
                int bb = m >> 11, t = m & (T_SEQ - 1);
                int h = n >> 6,  d = n & (D_KK - 1);
                C[(size_t)(((bb * N_HEADS + h) * T_SEQ) + t) * D_KK + d] = vv;
            } else {
                C[(size_t)m * N + n] = vv;
            }
        }
    }
}

/* ---------------- scores: P[bh, m, n] = (Q[bh,m,:] . K[bh,n,:]) / 8 ------ */
__global__ __launch_bounds__(256) void scores_kernel(
    const float* __restrict__ Q, const float* __restrict__ K,
    float* __restrict__ P)
{
    __shared__ float Qs[64][68]; /* [d][m] */
    __shared__ float Ks[64][68]; /* [d][n] */

    const int bh = blockIdx.z;
    const int m0 = blockIdx.y * 64, n0 = blockIdx.x * 64;
    const float* q = Q + (size_t)bh * T_SEQ * D_KK;
    const float* k = K + (size_t)bh * T_SEQ * D_KK;
    const int tid = threadIdx.x;

    #pragma unroll
    for (int u = 0; u < 4; u++) {
        int f = u * 256 + tid;            /* 0..1023 */
        int row = f >> 4;                 /* 0..63   */
        int c4 = (f & 15) * 4;            /* 0..60   */
        float4 qa = *(const float4*)&q[(size_t)(m0 + row) * D_KK + c4];
        Qs[c4 + 0][row] = qa.x; Qs[c4 + 1][row] = qa.y;
        Qs[c4 + 2][row] = qa.z; Qs[c4 + 3][row] = qa.w;
        float4 ka = *(const float4*)&k[(size_t)(n0 + row) * D_KK + c4];
        Ks[c4 + 0][row] = ka.x; Ks[c4 + 1][row] = ka.y;
        Ks[c4 + 2][row] = ka.z; Ks[c4 + 3][row] = ka.w;
    }
    __syncthreads();

    const int tx = tid & 15, ty = tid >> 4;
    float acc[4][4] = {};
    #pragma unroll
    for (int d = 0; d < 64; d++) {
        float4 a = *(const float4*)&Qs[d][ty * 4];
        float4 b = *(const float4*)&Ks[d][tx * 4];
        float aa[4] = {a.x, a.y, a.z, a.w};
        float bb[4] = {b.x, b.y, b.z, b.w};
        #pragma unroll
        for (int i = 0; i < 4; i++)
            #pragma unroll
            for (int j = 0; j < 4; j++)
                acc[i][j] = fmaf(aa[i], bb[j], acc[i][j]);
    }

    float* p = P + (size_t)bh * T_SEQ * T_SEQ;
    #pragma unroll
    for (int i = 0; i < 4; i++)
        #pragma unroll
        for (int j = 0; j < 4; j++)
            p[(size_t)(m0 + ty * 4 + i) * T_SEQ + n0 + tx * 4 + j] = acc[i][j] * 0.125f;
}

/* ---------------- softmax over last dim (2048), in place ------------------ */
__global__ __launch_bounds__(256) void softmax_kernel(float* __restrict__ P)
{
    float* p = P + (size_t)blockIdx.x * T_SEQ;
    const int tid = threadIdx.x;
    const int wid = tid >> 5, lane = tid & 31;
    __shared__ float red[8];

    float vals[8];
    float m = -1e30f;
    #pragma unroll
    for (int i = 0; i < 8; i++) {
        vals[i] = p[tid + i * 256];
        m = fmaxf(m, vals[i]);
    }
    m = warp_max(m);
    if (lane == 0) red[wid] = m;
    __syncthreads();
    if (tid == 0) {
        float mm = red[0];
        #pragma unroll
        for (int i = 1; i < 8; i++) mm = fmaxf(mm, red[i]);
        red[0] = mm;
    }
    __syncthreads();
    m = red[0];
    __syncthreads();

    float s = 0.0f;
    #pragma unroll
    for (int i = 0; i < 8; i++) {
        vals[i] = expf(vals[i] - m);
        s += vals[i];
    }
    s = warp_sum(s);
    if (lane == 0) red[wid] = s;
    __syncthreads();
    if (tid == 0) {
        float ss = 0.0f;
        #pragma unroll
        for (int i = 0; i < 8; i++) ss += red[i];
        red[0] = ss;
    }
    __syncthreads();
    float inv = 1.0f / red[0];
    #pragma unroll
    for (int i = 0; i < 8; i++) p[tid + i * 256] = vals[i] * inv;
}

/* ---------------- ctx: C[b, t, h*64+d] = sum_k P[bh,t,k] V[bh,k,d] -------- */
__global__ __launch_bounds__(256) void ctx_kernel(
    const float* __restrict__ P, const float* __restrict__ V,
    float* __restrict__ C)
{
    __shared__ float Ps[64][68]; /* [m][k] */
    __shared__ float Vs[64][68]; /* [k][n] */

    const int bh = blockIdx.z;
    const int m0 = blockIdx.y * 64;
    const float* p = P + (size_t)bh * T_SEQ * T_SEQ;
    const float* v = V + (size_t)bh * T_SEQ * D_KK;
    const int tid = threadIdx.x;
    const int tx = tid & 15, ty = tid >> 4;

    float acc[4][4] = {};
    for (int k0 = 0; k0 < T_SEQ; k0 += 64) {
        #pragma unroll
        for (int u = 0; u < 4; u++) {
            int f = u * 256 + tid;
            int row = f >> 4, c4 = (f & 15) * 4;
            *(float4*)&Ps[row][c4] = *(const float4*)&p[(size_t)(m0 + row) * T_SEQ + k0 + c4];
            *(float4*)&Vs[row][c4] = *(const float4*)&v[(size_t)(k0 + row) * D_KK + c4];
        }
        __syncthreads();
        #pragma unroll
        for (int kk = 0; kk < 64; kk++) {
            float aa[4] = {Ps[ty * 4 + 0][kk], Ps[ty * 4 + 1][kk],
                           Ps[ty * 4 + 2][kk], Ps[ty * 4 + 3][kk]};
            float4 b = *(const float4*)&Vs[kk][tx * 4];
            float bb[4] = {b.x, b.y, b.z, b.w};
            #pragma unroll
            for (int i = 0; i < 4; i++)
                #pragma unroll
                for (int j = 0; j < 4; j++)
                    acc[i][j] = fmaf(aa[i], bb[j], acc[i][j]);
        }
        __syncthreads();
    }

    const int b = bh >> 3, h = bh & 7;
    #pragma unroll
    for (int i = 0; i < 4; i++)
        #pragma unroll
        for (int j = 0; j < 4; j++)
            C[(size_t)(b * T_SEQ + m0 + ty * 4 + i) * D_MODEL + h * D_KK + tx * 4 + j] = acc[i][j];
}

/* ---------------- fused residual add + LayerNorm (row = 512) ------------- */
__global__ __launch_bounds__(128) void add_ln_kernel(
    const float* __restrict__ X, const float* __restrict__ Y,
    const float* __restrict__ g, const float* __restrict__ b,
    float* __restrict__ O)
{
    const int tid = threadIdx.x;
    const size_t base = (size_t)blockIdx.x * D_MODEL + tid * 4;
    float4 xv = *(const float4*)&X[base];
    float4 yv = *(const float4*)&Y[base];
    float4 v = make_float4(xv.x + yv.x, xv.y + yv.y, xv.z + yv.z, xv.w + yv.w);

    float s  = v.x + v.y + v.z + v.w;
    float ss = v.x * v.x + v.y * v.y + v.z * v.z + v.w * v.w;
    s = warp_sum(s);
    ss = warp_sum(ss);

    __shared__ float r1[4], r2[4];
    const int wid = tid >> 5, lane = tid & 31;
    if (lane == 0) { r1[wid] = s; r2[wid] = ss; }
    __syncthreads();
    if (tid == 0) {
        float a = 0.0f, c = 0.0f;
        #pragma unroll
        for (int i = 0; i < 4; i++) { a += r1[i]; c += r2[i]; }
        r1[0] = a; r2[0] = c;
    }
    __syncthreads();
    const float mu  = r1[0] * (1.0f / 512.0f);
    const float var = r2[0] * (1.0f / 512.0f) - mu * mu;
    const float rs  = rsqrtf(var + 1e-5f);

    float4 gv = *(const float4*)&g[tid * 4];
    float4 bv = *(const float4*)&b[tid * 4];
    float4 o;
    o.x = (v.x - mu) * rs * gv.x + bv.x;
    o.y = (v.y - mu) * rs * gv.y + bv.y;
    o.z = (v.z - mu) * rs * gv.z + bv.z;
    o.w = (v.w - mu) * rs * gv.w + bv.w;
    *(float4*)&O[base] = o;
}

/* ---------------- launch -------------------------------------------------- */
extern "C" void kernel_launch(void* const* d_in, const int* in_sizes, int n_in,
                              void* d_out, int out_size)
{
    const float* x     = (const float*)d_in[0];
    const float* wq_w  = (const float*)d_in[1];
    const float* wq_b  = (const float*)d_in[2];
    const float* wk_w  = (const float*)d_in[3];
    const float* wk_b  = (const float*)d_in[4];
    const float* wv_w  = (const float*)d_in[5];
    const float* wv_b  = (const float*)d_in[6];
    const float* wo_w  = (const float*)d_in[7];
    const float* wo_b  = (const float*)d_in[8];
    const float* ln1_g = (const float*)d_in[9];
    const float* ln1_b = (const float*)d_in[10];
    const float* fc1_w = (const float*)d_in[11];
    const float* fc1_b = (const float*)d_in[12];
    const float* fc2_w = (const float*)d_in[13];
    const float* fc2_b = (const float*)d_in[14];
    const float* ln2_g = (const float*)d_in[15];
    const float* ln2_b = (const float*)d_in[16];

    float* out = (float*)d_out;

    float *pq, *pk, *pv, *pctx, *ptmp, *ph, *pffn1;
    cudaGetSymbolAddress((void**)&pq,    g_q);
    cudaGetSymbolAddress((void**)&pk,    g_k);
    cudaGetSymbolAddress((void**)&pv,    g_v);
    cudaGetSymbolAddress((void**)&pctx,  g_ctx);
    cudaGetSymbolAddress((void**)&ptmp,  g_tmp);
    cudaGetSymbolAddress((void**)&ph,    g_h);
    cudaGetSymbolAddress((void**)&pffn1, g_ffn1);

    /* attn is the second output: write directly into d_out if it fits there */
    float* attn;
    if ((size_t)out_size >= OUT_ELEMS + ATTN_ELEMS) {
        attn = out + OUT_ELEMS;
    } else {
        cudaGetSymbolAddress((void**)&attn, g_attn_scratch);
    }

    /* QKV projections (scattered to [b,h,t,d]) */
    gemm_kernel<<<dim3(D_MODEL / 128, BT / 128), 256>>>(x, wq_w, wq_b, pq, BT, D_MODEL, D_MODEL, EPI_QKV);
    gemm_kernel<<<dim3(D_MODEL / 128, BT / 128), 256>>>(x, wk_w, wk_b, pk, BT, D_MODEL, D_MODEL, EPI_QKV);
    gemm_kernel<<<dim3(D_MODEL / 128, BT / 128), 256>>>(x, wv_w, wv_b, pv, BT, D_MODEL, D_MODEL, EPI_QKV);

    /* attention */
    scores_kernel<<<dim3(T_SEQ / 64, T_SEQ / 64, BH), 256>>>(pq, pk, attn);
    softmax_kernel<<<BH * T_SEQ, 256>>>(attn);
    ctx_kernel<<<dim3(1, T_SEQ / 64, BH), 256>>>(attn, pv, pctx);

    /* output projection + LN1 */
    gemm_kernel<<<dim3(D_MODEL / 128, BT / 128), 256>>>(pctx, wo_w, wo_b, ptmp, BT, D_MODEL, D_MODEL, EPI_NONE);
    add_ln_kernel<<<BT, 128>>>(x, ptmp, ln1_g, ln1_b, ph);

    /* FFN + LN2 */
    gemm_kernel<<<dim3(D_FF / 128, BT / 128), 256>>>(ph, fc1_w, fc1_b, pffn1, BT, D_FF, D_MODEL, EPI_RELU);
    gemm_kernel<<<dim3(D_MODEL / 128, BT / 128), 256>>>(pffn1, fc2_w, fc2_b, ptmp, BT, D_MODEL, D_FF, EPI_NONE);
    add_ln_kernel<<<BT, 128>>>(ph, ptmp, ln2_g, ln2_b, out);
}

// round 2
// speedup vs baseline: 2.0983x; 2.0983x over previous
#include <cuda_runtime.h>
#include <math.h>
#include <stdint.h>

#define D_MODEL 512
#define N_HEADS 8
#define D_KK    64
#define D_FF    2048
#define T_SEQ   2048
#define B_BATCH 2
#define BT      (B_BATCH * T_SEQ)    /* 4096 rows */
#define BH      (B_BATCH * N_HEADS)  /* 16 batched heads */

#define OUT_ELEMS  ((size_t)BT * D_MODEL)
#define ATTN_ELEMS ((size_t)BH * T_SEQ * T_SEQ)

/* EPI modes */
#define EPI_BIAS  0
#define EPI_RELU  1
#define EPI_QKV   2
#define EPI_SCALE 3
#define EPI_CTX   4

/* ---------------- scratch (device globals: no allocation allowed) -------- */
__device__ float g_q[BH * T_SEQ * D_KK];
__device__ float g_k[BH * T_SEQ * D_KK];
__device__ float g_v[BH * T_SEQ * D_KK];
__device__ float g_ctx[BT * D_MODEL];
__device__ float g_tmp[BT * D_MODEL];
__device__ float g_h[BT * D_MODEL];
__device__ float g_ffn1[BT * D_FF];
__device__ float g_attn_scratch[BH * (size_t)T_SEQ * T_SEQ];

/* ---------------- helpers ------------------------------------------------- */
__device__ __forceinline__ uint32_t f2tf(float f) {
    uint32_t r;
    asm("cvt.rna.tf32.f32 %0, %1;" : "=r"(r) : "f"(f));
    return r;
}
__device__ __forceinline__ void mma8(float c[4], uint32_t a0, uint32_t a1,
                                     uint32_t a2, uint32_t a3,
                                     uint32_t b0, uint32_t b1) {
    asm volatile(
        "mma.sync.aligned.m16n8k8.row.col.f32.tf32.tf32.f32 "
        "{%0,%1,%2,%3}, {%4,%5,%6,%7}, {%8,%9}, {%0,%1,%2,%3};"
        : "+f"(c[0]), "+f"(c[1]), "+f"(c[2]), "+f"(c[3])
        : "r"(a0), "r"(a1), "r"(a2), "r"(a3), "r"(b0), "r"(b1));
}
__device__ __forceinline__ float warp_sum(float v) {
    #pragma unroll
    for (int o = 16; o > 0; o >>= 1) v += __shfl_xor_sync(0xffffffffu, v, o);
    return v;
}
__device__ __forceinline__ float warp_max(float v) {
    #pragma unroll
    for (int o = 16; o > 0; o >>= 1) v = fmaxf(v, __shfl_xor_sync(0xffffffffu, v, o));
    return v;
}

/* ---------------- tf32 tensor-core GEMM ----------------------------------
 * C[M,N] = A[M,K] @ B + epilogue.
 * TRANSB=false: B is [K,N] row-major. TRANSB=true: B is [N,K] row-major.
 * Block tile 128 x BN x 32, 256 threads, m16n8k8 tf32 mma.
 * Smem stored k-major with stride = tile+8 (stride%32==8 -> conflict-free
 * fragment loads AND conflict-free stores).
 */
template <int BN, bool TRANSB, int EPI>
__global__ __launch_bounds__(256) void mma_gemm(
    const float* __restrict__ A, const float* __restrict__ B,
    const float* __restrict__ bias, float* __restrict__ C,
    int M, int N, int K, int lda, int ldb, int ldc,
    long azs, long bzs, long czs, float scale)
{
    constexpr int KT = 32;
    constexpr int SA = 136;       /* 128 + 8 */
    constexpr int SB = BN + 8;    /* 136 or 72 */
    constexpr int AM = (BN == 128) ? 2 : 1;

    __shared__ uint32_t As[KT][SA];
    __shared__ uint32_t Bs[KT][SB];

    const int tid = threadIdx.x;
    const int lane = tid & 31, wid = tid >> 5;
    const int z = blockIdx.z;
    A += (long)z * azs;
    B += (long)z * bzs;

    const int bm = blockIdx.y * 128;
    const int bn = blockIdx.x * BN;

    const int mb = (BN == 128) ? (wid & 3) * 32 : wid * 16;
    const int nb = (BN == 128) ? (wid >> 2) * 64 : 0;

    float acc[AM][8][4];
    #pragma unroll
    for (int i = 0; i < AM; i++)
        #pragma unroll
        for (int j = 0; j < 8; j++)
            #pragma unroll
            for (int r = 0; r < 4; r++) acc[i][j][r] = 0.0f;

    for (int k0 = 0; k0 < K; k0 += KT) {
        /* ---- A tile: 128 x 32 -> As[k][m] (transposed store) ---- */
        #pragma unroll
        for (int i = 0; i < 4; i++) {
            int f = tid + i * 256;               /* 0..1023 */
            int m = f & 127;
            int kk = (f >> 7) * 4;
            float4 v = *(const float4*)&A[(size_t)(bm + m) * lda + k0 + kk];
            As[kk + 0][m] = f2tf(v.x);
            As[kk + 1][m] = f2tf(v.y);
            As[kk + 2][m] = f2tf(v.z);
            As[kk + 3][m] = f2tf(v.w);
        }
        /* ---- B tile -> Bs[k][n] ---- */
        if (TRANSB) {
            /* B[N,K]: tile rows bn..bn+127, cols k0..k0+31 (BN==128 only) */
            #pragma unroll
            for (int i = 0; i < 4; i++) {
                int f = tid + i * 256;
                int n = f & 127;
                int kk = (f >> 7) * 4;
                float4 v = *(const float4*)&B[(size_t)(bn + n) * ldb + k0 + kk];
                Bs[kk + 0][n] = f2tf(v.x);
                Bs[kk + 1][n] = f2tf(v.y);
                Bs[kk + 2][n] = f2tf(v.z);
                Bs[kk + 3][n] = f2tf(v.w);
            }
        } else {
            /* B[K,N]: tile k0..k0+31 x bn..bn+BN-1 */
            constexpr int NV = BN / 4;                 /* float4 per row */
            #pragma unroll
            for (int i = 0; i < (KT * BN) / 1024; i++) {
                int f = tid + i * 256;
                int n4 = (f % NV) * 4;
                int kk = f / NV;
                float4 v = *(const float4*)&B[(size_t)(k0 + kk) * ldb + bn + n4];
                uint4 u;
                u.x = f2tf(v.x); u.y = f2tf(v.y); u.z = f2tf(v.z); u.w = f2tf(v.w);
                *(uint4*)&Bs[kk][n4] = u;
            }
        }
        __syncthreads();

        #pragma unroll
        for (int ks = 0; ks < KT / 8; ks++) {
            uint32_t af[AM][4], bf[8][2];
            #pragma unroll
            for (int am = 0; am < AM; am++)
                #pragma unroll
                for (int j = 0; j < 4; j++)
                    af[am][j] = As[ks * 8 + (lane & 3) + (j >> 1) * 4]
                                  [mb + am * 16 + (lane >> 2) + (j & 1) * 8];
            #pragma unroll
            for (int an = 0; an < 8; an++)
                #pragma unroll
                for (int j = 0; j < 2; j++)
                    bf[an][j] = Bs[ks * 8 + (lane & 3) + j * 4]
                                  [nb + an * 8 + (lane >> 2)];
            #pragma unroll
            for (int am = 0; am < AM; am++)
                #pragma unroll
                for (int an = 0; an < 8; an++)
                    mma8(acc[am][an], af[am][0], af[am][1], af[am][2], af[am][3],
                         bf[an][0], bf[an][1]);
        }
        __syncthreads();
    }

    /* ---- epilogue ---- */
    float* Cz;
    if (EPI == EPI_CTX) {
        int b = z >> 3, h = z & 7;
        Cz = C + (size_t)b * T_SEQ * D_MODEL + h * D_KK;
    } else {
        Cz = C + (long)z * czs;
    }

    #pragma unroll
    for (int am = 0; am < AM; am++)
        #pragma unroll
        for (int an = 0; an < 8; an++)
            #pragma unroll
            for (int half = 0; half < 2; half++) {
                int m = bm + mb + am * 16 + (lane >> 2) + half * 8;
                int c = bn + nb + an * 8 + (lane & 3) * 2;
                float v0 = acc[am][an][half * 2 + 0];
                float v1 = acc[am][an][half * 2 + 1];
                if (EPI == EPI_SCALE) { v0 *= scale; v1 *= scale; }
                if (EPI == EPI_BIAS || EPI == EPI_RELU || EPI == EPI_QKV) {
                    v0 += bias[c]; v1 += bias[c + 1];
                }
                if (EPI == EPI_RELU) { v0 = fmaxf(v0, 0.0f); v1 = fmaxf(v1, 0.0f); }
                if (EPI == EPI_QKV) {
                    int bb = m >> 11, t = m & (T_SEQ - 1);
                    int h = c >> 6, d = c & (D_KK - 1);
                    float2* dst = (float2*)&Cz[((size_t)((bb * N_HEADS + h) * T_SEQ) + t) * D_KK + d];
                    *dst = make_float2(v0, v1);
                } else {
                    *(float2*)&Cz[(size_t)m * ldc + c] = make_float2(v0, v1);
                }
            }
}

/* ---------------- softmax over last dim (2048), in place ------------------ */
__global__ __launch_bounds__(256) void softmax_kernel(float* __restrict__ P)
{
    float* p = P + (size_t)blockIdx.x * T_SEQ;
    const int tid = threadIdx.x;
    const int wid = tid >> 5, lane = tid & 31;
    __shared__ float red[8];

    float vals[8];
    float m = -1e30f;
    #pragma unroll
    for (int i = 0; i < 8; i++) {
        vals[i] = p[tid + i * 256];
        m = fmaxf(m, vals[i]);
    }
    m = warp_max(m);
    if (lane == 0) red[wid] = m;
    __syncthreads();
    if (tid == 0) {
        float mm = red[0];
        #pragma unroll
        for (int i = 1; i < 8; i++) mm = fmaxf(mm, red[i]);
        red[0] = mm;
    }
    __syncthreads();
    m = red[0];
    __syncthreads();

    float s = 0.0f;
    #pragma unroll
    for (int i = 0; i < 8; i++) {
        vals[i] = expf(vals[i] - m);
        s += vals[i];
    }
    s = warp_sum(s);
    if (lane == 0) red[wid] = s;
    __syncthreads();
    if (tid == 0) {
        float ss = 0.0f;
        #pragma unroll
        for (int i = 0; i < 8; i++) ss += red[i];
        red[0] = ss;
    }
    __syncthreads();
    float inv = 1.0f / red[0];
    #pragma unroll
    for (int i = 0; i < 8; i++) p[tid + i * 256] = vals[i] * inv;
}

/* ---------------- fused residual add + LayerNorm (row = 512) ------------- */
__global__ __launch_bounds__(128) void add_ln_kernel(
    const float* __restrict__ X, const float* __restrict__ Y,
    const float* __restrict__ g, const float* __restrict__ b,
    float* __restrict__ O)
{
    const int tid = threadIdx.x;
    const size_t base = (size_t)blockIdx.x * D_MODEL + tid * 4;
    float4 xv = *(const float4*)&X[base];
    float4 yv = *(const float4*)&Y[base];
    float4 v = make_float4(xv.x + yv.x, xv.y + yv.y, xv.z + yv.z, xv.w + yv.w);

    float s  = v.x + v.y + v.z + v.w;
    float ss = v.x * v.x + v.y * v.y + v.z * v.z + v.w * v.w;
    s = warp_sum(s);
    ss = warp_sum(ss);

    __shared__ float r1[4], r2[4];
    const int wid = tid >> 5, lane = tid & 31;
    if (lane == 0) { r1[wid] = s; r2[wid] = ss; }
    __syncthreads();
    if (tid == 0) {
        float a = 0.0f, c = 0.0f;
        #pragma unroll
        for (int i = 0; i < 4; i++) { a += r1[i]; c += r2[i]; }
        r1[0] = a; r2[0] = c;
    }
    __syncthreads();
    const float mu  = r1[0] * (1.0f / 512.0f);
    const float var = r2[0] * (1.0f / 512.0f) - mu * mu;
    const float rs  = rsqrtf(var + 1e-5f);

    float4 gv = *(const float4*)&g[tid * 4];
    float4 bv = *(const float4*)&b[tid * 4];
    float4 o;
    o.x = (v.x - mu) * rs * gv.x + bv.x;
    o.y = (v.y - mu) * rs * gv.y + bv.y;
    o.z = (v.z - mu) * rs * gv.z + bv.z;
    o.w = (v.w - mu) * rs * gv.w + bv.w;
    *(float4*)&O[base] = o;
}

/* ---------------- launch -------------------------------------------------- */
extern "C" void kernel_launch(void* const* d_in, const int* in_sizes, int n_in,
                              void* d_out, int out_size)
{
    const float* x     = (const float*)d_in[0];
    const float* wq_w  = (const float*)d_in[1];
    const float* wq_b  = (const float*)d_in[2];
    const float* wk_w  = (const float*)d_in[3];
    const float* wk_b  = (const float*)d_in[4];
    const float* wv_w  = (const float*)d_in[5];
    const float* wv_b  = (const float*)d_in[6];
    const float* wo_w  = (const float*)d_in[7];
    const float* wo_b  = (const float*)d_in[8];
    const float* ln1_g = (const float*)d_in[9];
    const float* ln1_b = (const float*)d_in[10];
    const float* fc1_w = (const float*)d_in[11];
    const float* fc1_b = (const float*)d_in[12];
    const float* fc2_w = (const float*)d_in[13];
    const float* fc2_b = (const float*)d_in[14];
    const float* ln2_g = (const float*)d_in[15];
    const float* ln2_b = (const float*)d_in[16];

    float* out = (float*)d_out;

    float *pq, *pk, *pv, *pctx, *ptmp, *ph, *pffn1;
    cudaGetSymbolAddress((void**)&pq,    g_q);
    cudaGetSymbolAddress((void**)&pk,    g_k);
    cudaGetSymbolAddress((void**)&pv,    g_v);
    cudaGetSymbolAddress((void**)&pctx,  g_ctx);
    cudaGetSymbolAddress((void**)&ptmp,  g_tmp);
    cudaGetSymbolAddress((void**)&ph,    g_h);
    cudaGetSymbolAddress((void**)&pffn1, g_ffn1);

    float* attn;
    if ((size_t)out_size >= OUT_ELEMS + ATTN_ELEMS) {
        attn = out + OUT_ELEMS;
    } else {
        cudaGetSymbolAddress((void**)&attn, g_attn_scratch);
    }

    /* QKV projections (scatter to [b,h,t,d]) */
    mma_gemm<128, false, EPI_QKV><<<dim3(4, 32, 1), 256>>>(
        x, wq_w, wq_b, pq, BT, D_MODEL, D_MODEL, D_MODEL, D_MODEL, D_MODEL, 0, 0, 0, 1.0f);
    mma_gemm<128, false, EPI_QKV><<<dim3(4, 32, 1), 256>>>(
        x, wk_w, wk_b, pk, BT, D_MODEL, D_MODEL, D_MODEL, D_MODEL, D_MODEL, 0, 0, 0, 1.0f);
    mma_gemm<128, false, EPI_QKV><<<dim3(4, 32, 1), 256>>>(
        x, wv_w, wv_b, pv, BT, D_MODEL, D_MODEL, D_MODEL, D_MODEL, D_MODEL, 0, 0, 0, 1.0f);

    /* scores: P = Q @ K^T / 8  (batched over 16 heads) */
    mma_gemm<128, true, EPI_SCALE><<<dim3(16, 16, BH), 256>>>(
        pq, pk, nullptr, attn, T_SEQ, T_SEQ, D_KK, D_KK, D_KK, T_SEQ,
        (long)T_SEQ * D_KK, (long)T_SEQ * D_KK, (long)T_SEQ * T_SEQ, 0.125f);

    softmax_kernel<<<BH * T_SEQ, 256>>>(attn);

    /* ctx: C = P @ V  (batched; scattered into [b,t,h*64+d]) */
    mma_gemm<64, false, EPI_CTX><<<dim3(1, 16, BH), 256>>>(
        attn, pv, nullptr, pctx, T_SEQ, D_KK, T_SEQ, T_SEQ, D_KK, D_MODEL,
        (long)T_SEQ * T_SEQ, (long)T_SEQ * D_KK, 0, 1.0f);

    /* output projection + LN1 */
    mma_gemm<128, false, EPI_BIAS><<<dim3(4, 32, 1), 256>>>(
        pctx, wo_w, wo_b, ptmp, BT, D_MODEL, D_MODEL, D_MODEL, D_MODEL, D_MODEL, 0, 0, 0, 1.0f);
    add_ln_kernel<<<BT, 128>>>(x, ptmp, ln1_g, ln1_b, ph);

    /* FFN + LN2 */
    mma_gemm<128, false, EPI_RELU><<<dim3(16, 32, 1), 256>>>(
        ph, fc1_w, fc1_b, pffn1, BT, D_FF, D_MODEL, D_MODEL, D_FF, D_FF, 0, 0, 0, 1.0f);
    mma_gemm<128, false, EPI_BIAS><<<dim3(4, 32, 1), 256>>>(
        pffn1, fc2_w, fc2_b, ptmp, BT, D_MODEL, D_FF, D_FF, D_MODEL, D_MODEL, 0, 0, 0, 1.0f);
    add_ln_kernel<<<BT, 128>>>(ph, ptmp, ln2_g, ln2_b, out);
}

// round 3
// speedup vs baseline: 2.7967x; 1.3328x over previous
#include <cuda_runtime.h>
#include <math.h>
#include <stdint.h>

#define D_MODEL 512
#define N_HEADS 8
#define D_KK    64
#define D_FF    2048
#define T_SEQ   2048
#define B_BATCH 2
#define BT      (B_BATCH * T_SEQ)
#define BH      (B_BATCH * N_HEADS)

#define OUT_ELEMS  ((size_t)BT * D_MODEL)
#define ATTN_ELEMS ((size_t)BH * T_SEQ * T_SEQ)

#define EPI_BIAS   0
#define EPI_RELU   1
#define EPI_QKV    2
#define EPI_EXPSUM 3

#define LOG2E 1.4426950408889634f

/* ---------------- scratch ------------------------------------------------- */
__device__ float g_q[BH * T_SEQ * D_KK];
__device__ float g_k[BH * T_SEQ * D_KK];
__device__ float g_v[BH * T_SEQ * D_KK];
__device__ float g_ctx[BT * D_MODEL];
__device__ float g_tmp[BT * D_MODEL];
__device__ float g_h[BT * D_MODEL];
__device__ float g_ffn1[BT * D_FF];
__device__ float g_psum[(size_t)BH * T_SEQ * 32];
__device__ float g_invsum[(size_t)BH * T_SEQ];
__device__ float g_attn_scratch[BH * (size_t)T_SEQ * T_SEQ];

/* ---------------- helpers ------------------------------------------------- */
__device__ __forceinline__ uint32_t f2tf(float f) {
    uint32_t r;
    asm("cvt.rna.tf32.f32 %0, %1;" : "=r"(r) : "f"(f));
    return r;
}
__device__ __forceinline__ void mma8(float c[4], uint32_t a0, uint32_t a1,
                                     uint32_t a2, uint32_t a3,
                                     uint32_t b0, uint32_t b1) {
    asm volatile(
        "mma.sync.aligned.m16n8k8.row.col.f32.tf32.tf32.f32 "
        "{%0,%1,%2,%3}, {%4,%5,%6,%7}, {%8,%9}, {%0,%1,%2,%3};"
        : "+f"(c[0]), "+f"(c[1]), "+f"(c[2]), "+f"(c[3])
        : "r"(a0), "r"(a1), "r"(a2), "r"(a3), "r"(b0), "r"(b1));
}
__device__ __forceinline__ void cp16(float* sdst, const float* gsrc) {
    uint32_t s = (uint32_t)__cvta_generic_to_shared(sdst);
    asm volatile("cp.async.cg.shared.global [%0], [%1], 16;" :: "r"(s), "l"(gsrc));
}
__device__ __forceinline__ float warp_sum(float v) {
    #pragma unroll
    for (int o = 16; o > 0; o >>= 1) v += __shfl_xor_sync(0xffffffffu, v, o);
    return v;
}

/* ---------------- cp.async double-buffered tf32 GEMM ---------------------
 * C[M,N] = A[M,K] @ B + epilogue. Block tile 128x128x32, 256 threads.
 * Smem holds raw fp32; tf32 convert at fragment load.
 * A stored [m][k] stride 36 (cf-free: bank = 4m+k), B non-trans [k][n]
 * stride 136 (bank = 8k+n), B trans [n][k] stride 36.
 */
template <bool TRANSB, int EPI>
__global__ __launch_bounds__(256) void mma_gemm(
    const float* __restrict__ A, const float* __restrict__ B,
    const float* __restrict__ bias, float* __restrict__ C,
    float* __restrict__ psum,
    int M, int N, int K, int lda, int ldb, int ldc,
    long azs, long bzs, long czs, float scale)
{
    constexpr int KT  = 32;
    constexpr int SA  = KT + 4;                         /* 36 */
    constexpr int SBk = 128 + 8;                        /* 136 */
    constexpr int A_ELE = 128 * SA;                     /* 4608 */
    constexpr int B_ELE = TRANSB ? (128 * SA) : (KT * SBk);
    constexpr int STG = A_ELE + B_ELE;

    extern __shared__ float smem[];

    const int tid = threadIdx.x;
    const int lane = tid & 31, wid = tid >> 5;
    const int z = blockIdx.z;
    A += (long)z * azs;
    B += (long)z * bzs;

    const int bm = blockIdx.y * 128;
    const int bn = blockIdx.x * 128;
    const int mb = (wid & 3) * 32;
    const int nb = (wid >> 2) * 64;

    float acc[2][8][4];
    #pragma unroll
    for (int i = 0; i < 2; i++)
        #pragma unroll
        for (int j = 0; j < 8; j++)
            #pragma unroll
            for (int r = 0; r < 4; r++) acc[i][j][r] = 0.0f;

    auto issue = [&](int k0, int st) {
        float* As = smem + st * STG;
        float* Bs = As + A_ELE;
        #pragma unroll
        for (int i = 0; i < 4; i++) {
            int f = tid + i * 256;
            int m = f >> 3, k4 = (f & 7) * 4;
            cp16(&As[m * SA + k4], &A[(size_t)(bm + m) * lda + k0 + k4]);
        }
        if (TRANSB) {
            #pragma unroll
            for (int i = 0; i < 4; i++) {
                int f = tid + i * 256;
                int n = f >> 3, k4 = (f & 7) * 4;
                cp16(&Bs[n * SA + k4], &B[(size_t)(bn + n) * ldb + k0 + k4]);
            }
        } else {
            #pragma unroll
            for (int i = 0; i < 4; i++) {
                int f = tid + i * 256;
                int kk = f >> 5, n4 = (f & 31) * 4;
                cp16(&Bs[kk * SBk + n4], &B[(size_t)(k0 + kk) * ldb + bn + n4]);
            }
        }
        asm volatile("cp.async.commit_group;" ::: "memory");
    };

    issue(0, 0);
    const int nIter = K / KT;
    for (int it = 0; it < nIter; it++) {
        if (it + 1 < nIter) {
            issue((it + 1) * KT, (it + 1) & 1);
            asm volatile("cp.async.wait_group 1;" ::: "memory");
        } else {
            asm volatile("cp.async.wait_group 0;" ::: "memory");
        }
        __syncthreads();

        float* As = smem + (it & 1) * STG;
        float* Bs = As + A_ELE;
        #pragma unroll
        for (int ks = 0; ks < KT / 8; ks++) {
            uint32_t af[2][4], bf[8][2];
            #pragma unroll
            for (int am = 0; am < 2; am++)
                #pragma unroll
                for (int j = 0; j < 4; j++)
                    af[am][j] = f2tf(As[(mb + am * 16 + (lane >> 2) + (j & 1) * 8) * SA
                                        + ks * 8 + (lane & 3) + (j >> 1) * 4]);
            #pragma unroll
            for (int an = 0; an < 8; an++)
                #pragma unroll
                for (int j = 0; j < 2; j++)
                    bf[an][j] = TRANSB
                        ? f2tf(Bs[(nb + an * 8 + (lane >> 2)) * SA + ks * 8 + (lane & 3) + j * 4])
                        : f2tf(Bs[(ks * 8 + (lane & 3) + j * 4) * SBk + nb + an * 8 + (lane >> 2)]);
            #pragma unroll
            for (int am = 0; am < 2; am++)
                #pragma unroll
                for (int an = 0; an < 8; an++)
                    mma8(acc[am][an], af[am][0], af[am][1], af[am][2], af[am][3],
                         bf[an][0], bf[an][1]);
        }
        __syncthreads();
    }

    /* ---- epilogue ---- */
    float* Cz = C + (long)z * czs;

    if (EPI == EPI_EXPSUM) {
        #pragma unroll
        for (int am = 0; am < 2; am++)
            #pragma unroll
            for (int half = 0; half < 2; half++) {
                int m = bm + mb + am * 16 + (lane >> 2) + half * 8;
                float rs = 0.0f;
                #pragma unroll
                for (int an = 0; an < 8; an++) {
                    int c = bn + nb + an * 8 + (lane & 3) * 2;
                    float e0 = exp2f(acc[am][an][half * 2 + 0] * scale);
                    float e1 = exp2f(acc[am][an][half * 2 + 1] * scale);
                    *(float2*)&Cz[(size_t)m * ldc + c] = make_float2(e0, e1);
                    rs += e0 + e1;
                }
                rs += __shfl_xor_sync(0xffffffffu, rs, 1);
                rs += __shfl_xor_sync(0xffffffffu, rs, 2);
                if ((lane & 3) == 0)
                    psum[((size_t)z * T_SEQ + m) * 32 + blockIdx.x * 2 + (wid >> 2)] = rs;
            }
        return;
    }

    #pragma unroll
    for (int am = 0; am < 2; am++)
        #pragma unroll
        for (int an = 0; an < 8; an++)
            #pragma unroll
            for (int half = 0; half < 2; half++) {
                int m = bm + mb + am * 16 + (lane >> 2) + half * 8;
                int c = bn + nb + an * 8 + (lane & 3) * 2;
                float v0 = acc[am][an][half * 2 + 0];
                float v1 = acc[am][an][half * 2 + 1];
                if (EPI == EPI_BIAS || EPI == EPI_RELU || EPI == EPI_QKV) {
                    v0 += bias[c]; v1 += bias[c + 1];
                }
                if (EPI == EPI_RELU) { v0 = fmaxf(v0, 0.0f); v1 = fmaxf(v1, 0.0f); }
                if (EPI == EPI_QKV) {
                    int bb = m >> 11, t = m & (T_SEQ - 1);
                    int h = c >> 6, d = c & (D_KK - 1);
                    *(float2*)&Cz[((size_t)((bb * N_HEADS + h) * T_SEQ) + t) * D_KK + d]
                        = make_float2(v0, v1);
                } else {
                    *(float2*)&Cz[(size_t)m * ldc + c] = make_float2(v0, v1);
                }
            }
}

/* ---------------- rowsum reduce + invert --------------------------------- */
__global__ __launch_bounds__(128) void rowsum_inv_kernel(
    const float* __restrict__ psum, float* __restrict__ inv)
{
    int r = blockIdx.x * 128 + threadIdx.x;
    const float4* p = (const float4*)(psum + (size_t)r * 32);
    float s = 0.0f;
    #pragma unroll
    for (int i = 0; i < 8; i++) {
        float4 v = p[i];
        s += v.x + v.y + v.z + v.w;
    }
    inv[r] = 1.0f / s;
}

/* ---------------- fused normalize + attn write + P@V --------------------- */
__global__ __launch_bounds__(256) void attn_pv_kernel(
    float* __restrict__ attn, const float* __restrict__ V,
    const float* __restrict__ inv, float* __restrict__ ctx)
{
    constexpr int SA = 132;   /* [m][k] 128+4 : bank = 4m+k, cf-free */
    constexpr int SV = 72;    /* [k][n]  64+8 : bank = 8k+n, cf-free */
    extern __shared__ float sm[];
    float* As   = sm;                        /* 128*132 */
    float* Vs   = sm + 128 * SA;             /* 128*72  */
    float* invs = Vs + 128 * SV;             /* 128     */

    const int tid = threadIdx.x;
    const int lane = tid & 31, wid = tid >> 5;
    const int bm = blockIdx.x * 128;
    const int z = blockIdx.y;
    attn += (size_t)z * T_SEQ * T_SEQ;
    V    += (size_t)z * T_SEQ * D_KK;

    if (tid < 128) invs[tid] = inv[(size_t)z * T_SEQ + bm + tid];
    __syncthreads();

    const int mb = wid * 16;
    float acc[8][4];
    #pragma unroll
    for (int j = 0; j < 8; j++)
        #pragma unroll
        for (int r = 0; r < 4; r++) acc[j][r] = 0.0f;

    for (int k0 = 0; k0 < T_SEQ; k0 += 128) {
        #pragma unroll
        for (int i = 0; i < 16; i++) {
            int f = tid + i * 256;
            int m = f >> 5, k4 = (f & 31) * 4;
            size_t gi = (size_t)(bm + m) * T_SEQ + k0 + k4;
            float4 v = *(const float4*)&attn[gi];
            float iv = invs[m];
            v.x *= iv; v.y *= iv; v.z *= iv; v.w *= iv;
            *(float4*)&attn[gi] = v;
            *(float4*)&As[m * SA + k4] = v;
        }
        #pragma unroll
        for (int i = 0; i < 8; i++) {
            int f = tid + i * 256;
            int kk = f >> 4, c4 = (f & 15) * 4;
            *(float4*)&Vs[kk * SV + c4] = *(const float4*)&V[(size_t)(k0 + kk) * D_KK + c4];
        }
        __syncthreads();

        #pragma unroll
        for (int ks = 0; ks < 16; ks++) {
            uint32_t af[4], bf[8][2];
            #pragma unroll
            for (int j = 0; j < 4; j++)
                af[j] = f2tf(As[(mb + (lane >> 2) + (j & 1) * 8) * SA
                                + ks * 8 + (lane & 3) + (j >> 1) * 4]);
            #pragma unroll
            for (int an = 0; an < 8; an++)
                #pragma unroll
                for (int j = 0; j < 2; j++)
                    bf[an][j] = f2tf(Vs[(ks * 8 + (lane & 3) + j * 4) * SV
                                        + an * 8 + (lane >> 2)]);
            #pragma unroll
            for (int an = 0; an < 8; an++)
                mma8(acc[an], af[0], af[1], af[2], af[3], bf[an][0], bf[an][1]);
        }
        __syncthreads();
    }

    const int b = z >> 3, h = z & 7;
    float* Cz = ctx + (size_t)b * T_SEQ * D_MODEL + h * D_KK;
    #pragma unroll
    for (int an = 0; an < 8; an++)
        #pragma unroll
        for (int half = 0; half < 2; half++) {
            int m = bm + mb + (lane >> 2) + half * 8;
            int c = an * 8 + (lane & 3) * 2;
            *(float2*)&Cz[(size_t)m * D_MODEL + c]
                = make_float2(acc[an][half * 2 + 0], acc[an][half * 2 + 1]);
        }
}

/* ---------------- fused residual add + LayerNorm ------------------------- */
__global__ __launch_bounds__(128) void add_ln_kernel(
    const float* __restrict__ X, const float* __restrict__ Y,
    const float* __restrict__ g, const float* __restrict__ b,
    float* __restrict__ O)
{
    const int tid = threadIdx.x;
    const size_t base = (size_t)blockIdx.x * D_MODEL + tid * 4;
    float4 xv = *(const float4*)&X[base];
    float4 yv = *(const float4*)&Y[base];
    float4 v = make_float4(xv.x + yv.x, xv.y + yv.y, xv.z + yv.z, xv.w + yv.w);

    float s  = v.x + v.y + v.z + v.w;
    float ss = v.x * v.x + v.y * v.y + v.z * v.z + v.w * v.w;
    s = warp_sum(s);
    ss = warp_sum(ss);

    __shared__ float r1[4], r2[4];
    const int wid = tid >> 5, lane = tid & 31;
    if (lane == 0) { r1[wid] = s; r2[wid] = ss; }
    __syncthreads();
    if (tid == 0) {
        float a = 0.0f, c = 0.0f;
        #pragma unroll
        for (int i = 0; i < 4; i++) { a += r1[i]; c += r2[i]; }
        r1[0] = a; r2[0] = c;
    }
    __syncthreads();
    const float mu  = r1[0] * (1.0f / 512.0f);
    const float var = r2[0] * (1.0f / 512.0f) - mu * mu;
    const float rs  = rsqrtf(var + 1e-5f);

    float4 gv = *(const float4*)&g[tid * 4];
    float4 bv = *(const float4*)&b[tid * 4];
    float4 o;
    o.x = (v.x - mu) * rs * gv.x + bv.x;
    o.y = (v.y - mu) * rs * gv.y + bv.y;
    o.z = (v.z - mu) * rs * gv.z + bv.z;
    o.w = (v.w - mu) * rs * gv.w + bv.w;
    *(float4*)&O[base] = o;
}

/* ---------------- launch -------------------------------------------------- */
#define SMEM_NT 71680   /* 2*(128*36 + 32*136)*4 */
#define SMEM_TR 73728   /* 2*(128*36 + 128*36)*4 */
#define SMEM_PV 104960  /* (128*132 + 128*72 + 128)*4 */

extern "C" void kernel_launch(void* const* d_in, const int* in_sizes, int n_in,
                              void* d_out, int out_size)
{
    const float* x     = (const float*)d_in[0];
    const float* wq_w  = (const float*)d_in[1];
    const float* wq_b  = (const float*)d_in[2];
    const float* wk_w  = (const float*)d_in[3];
    const float* wk_b  = (const float*)d_in[4];
    const float* wv_w  = (const float*)d_in[5];
    const float* wv_b  = (const float*)d_in[6];
    const float* wo_w  = (const float*)d_in[7];
    const float* wo_b  = (const float*)d_in[8];
    const float* ln1_g = (const float*)d_in[9];
    const float* ln1_b = (const float*)d_in[10];
    const float* fc1_w = (const float*)d_in[11];
    const float* fc1_b = (const float*)d_in[12];
    const float* fc2_w = (const float*)d_in[13];
    const float* fc2_b = (const float*)d_in[14];
    const float* ln2_g = (const float*)d_in[15];
    const float* ln2_b = (const float*)d_in[16];

    float* out = (float*)d_out;

    float *pq, *pk, *pv, *pctx, *ptmp, *ph, *pffn1, *ppsum, *pinv;
    cudaGetSymbolAddress((void**)&pq,    g_q);
    cudaGetSymbolAddress((void**)&pk,    g_k);
    cudaGetSymbolAddress((void**)&pv,    g_v);
    cudaGetSymbolAddress((void**)&pctx,  g_ctx);
    cudaGetSymbolAddress((void**)&ptmp,  g_tmp);
    cudaGetSymbolAddress((void**)&ph,    g_h);
    cudaGetSymbolAddress((void**)&pffn1, g_ffn1);
    cudaGetSymbolAddress((void**)&ppsum, g_psum);
    cudaGetSymbolAddress((void**)&pinv,  g_invsum);

    float* attn;
    if ((size_t)out_size >= OUT_ELEMS + ATTN_ELEMS) {
        attn = out + OUT_ELEMS;
    } else {
        cudaGetSymbolAddress((void**)&attn, g_attn_scratch);
    }

    cudaFuncSetAttribute(mma_gemm<false, EPI_QKV>,
                         cudaFuncAttributeMaxDynamicSharedMemorySize, SMEM_NT);
    cudaFuncSetAttribute(mma_gemm<false, EPI_BIAS>,
                         cudaFuncAttributeMaxDynamicSharedMemorySize, SMEM_NT);
    cudaFuncSetAttribute(mma_gemm<false, EPI_RELU>,
                         cudaFuncAttributeMaxDynamicSharedMemorySize, SMEM_NT);
    cudaFuncSetAttribute(mma_gemm<true, EPI_EXPSUM>,
                         cudaFuncAttributeMaxDynamicSharedMemorySize, SMEM_TR);
    cudaFuncSetAttribute(attn_pv_kernel,
                         cudaFuncAttributeMaxDynamicSharedMemorySize, SMEM_PV);

    /* QKV projections (scatter to [b,h,t,d]) */
    mma_gemm<false, EPI_QKV><<<dim3(4, 32, 1), 256, SMEM_NT>>>(
        x, wq_w, wq_b, pq, nullptr, BT, D_MODEL, D_MODEL, D_MODEL, D_MODEL, D_MODEL, 0, 0, 0, 1.0f);
    mma_gemm<false, EPI_QKV><<<dim3(4, 32, 1), 256, SMEM_NT>>>(
        x, wk_w, wk_b, pk, nullptr, BT, D_MODEL, D_MODEL, D_MODEL, D_MODEL, D_MODEL, 0, 0, 0, 1.0f);
    mma_gemm<false, EPI_QKV><<<dim3(4, 32, 1), 256, SMEM_NT>>>(
        x, wv_w, wv_b, pv, nullptr, BT, D_MODEL, D_MODEL, D_MODEL, D_MODEL, D_MODEL, 0, 0, 0, 1.0f);

    /* scores + exp + partial row sums: attn <- exp(QK^T/8) */
    mma_gemm<true, EPI_EXPSUM><<<dim3(16, 16, BH), 256, SMEM_TR>>>(
        pq, pk, nullptr, attn, ppsum, T_SEQ, T_SEQ, D_KK, D_KK, D_KK, T_SEQ,
        (long)T_SEQ * D_KK, (long)T_SEQ * D_KK, (long)T_SEQ * T_SEQ,
        0.125f * LOG2E);

    rowsum_inv_kernel<<<(BH * T_SEQ) / 128, 128>>>(ppsum, pinv);

    /* normalize attn in place + ctx = P @ V */
    attn_pv_kernel<<<dim3(T_SEQ / 128, BH), 256, SMEM_PV>>>(attn, pv, pinv, pctx);

    /* output projection + LN1 */
    mma_gemm<false, EPI_BIAS><<<dim3(4, 32, 1), 256, SMEM_NT>>>(
        pctx, wo_w, wo_b, ptmp, nullptr, BT, D_MODEL, D_MODEL, D_MODEL, D_MODEL, D_MODEL, 0, 0, 0, 1.0f);
    add_ln_kernel<<<BT, 128>>>(x, ptmp, ln1_g, ln1_b, ph);

    /* FFN + LN2 */
    mma_gemm<false, EPI_RELU><<<dim3(16, 32, 1), 256, SMEM_NT>>>(
        ph, fc1_w, fc1_b, pffn1, nullptr, BT, D_FF, D_MODEL, D_MODEL, D_FF, D_FF, 0, 0, 0, 1.0f);
    mma_gemm<false, EPI_BIAS><<<dim3(4, 32, 1), 256, SMEM_NT>>>(
        pffn1, fc2_w, fc2_b, ptmp, nullptr, BT, D_MODEL, D_FF, D_FF, D_MODEL, D_MODEL, 0, 0, 0, 1.0f);
    add_ln_kernel<<<BT, 128>>>(ph, ptmp, ln2_g, ln2_b, out);
}

// round 4
// speedup vs baseline: 3.3179x; 1.1864x over previous
#include <cuda_runtime.h>
#include <math.h>
#include <stdint.h>

#define D_MODEL 512
#define N_HEADS 8
#define D_KK    64
#define D_FF    2048
#define T_SEQ   2048
#define B_BATCH 2
#define BT      (B_BATCH * T_SEQ)
#define BH      (B_BATCH * N_HEADS)

#define OUT_ELEMS  ((size_t)BT * D_MODEL)
#define ATTN_ELEMS ((size_t)BH * T_SEQ * T_SEQ)

#define EPI_BIAS   0
#define EPI_RELU   1
#define EPI_QKV    2

#define LOG2E 1.4426950408889634f

/* ---------------- scratch ------------------------------------------------- */
__device__ float g_q[BH * T_SEQ * D_KK];
__device__ float g_k[BH * T_SEQ * D_KK];
__device__ float g_v[BH * T_SEQ * D_KK];
__device__ float g_ctx[BT * D_MODEL];
__device__ float g_tmp[BT * D_MODEL];
__device__ float g_h[BT * D_MODEL];
__device__ float g_ffn1[BT * D_FF];
__device__ float g_psum[(size_t)BH * T_SEQ * 64];
__device__ float g_invsum[(size_t)BH * T_SEQ];
__device__ float g_attn_scratch[BH * (size_t)T_SEQ * T_SEQ];

/* ---------------- helpers ------------------------------------------------- */
__device__ __forceinline__ uint32_t f2tf(float f) {
    uint32_t r;
    asm("cvt.rna.tf32.f32 %0, %1;" : "=r"(r) : "f"(f));
    return r;
}
__device__ __forceinline__ void mma8(float c[4], uint32_t a0, uint32_t a1,
                                     uint32_t a2, uint32_t a3,
                                     uint32_t b0, uint32_t b1) {
    asm volatile(
        "mma.sync.aligned.m16n8k8.row.col.f32.tf32.tf32.f32 "
        "{%0,%1,%2,%3}, {%4,%5,%6,%7}, {%8,%9}, {%0,%1,%2,%3};"
        : "+f"(c[0]), "+f"(c[1]), "+f"(c[2]), "+f"(c[3])
        : "r"(a0), "r"(a1), "r"(a2), "r"(a3), "r"(b0), "r"(b1));
}
__device__ __forceinline__ void cp16(float* sdst, const float* gsrc) {
    uint32_t s = (uint32_t)__cvta_generic_to_shared(sdst);
    asm volatile("cp.async.cg.shared.global [%0], [%1], 16;" :: "r"(s), "l"(gsrc));
}
__device__ __forceinline__ float warp_sum(float v) {
    #pragma unroll
    for (int o = 16; o > 0; o >>= 1) v += __shfl_xor_sync(0xffffffffu, v, o);
    return v;
}

/* ---------------- cp.async double-buffered tf32 GEMM ---------------------
 * C[M,N] = A[M,K] @ B + epilogue. Block tile BM x 128 x 32, 256 threads.
 * z = blockIdx.z selects (B, bias, C) triple -> QKV in one launch.
 * A smem [m][k] stride 36 (bank = 4m+k cf-free); B smem [k][n] stride 136
 * (bank = 8k+n cf-free).
 */
template <int BM, int EPI>
__global__ __launch_bounds__(256) void mma_gemm(
    const float* __restrict__ A,
    const float* __restrict__ B0, const float* __restrict__ B1, const float* __restrict__ B2,
    const float* __restrict__ bias0, const float* __restrict__ bias1, const float* __restrict__ bias2,
    float* __restrict__ C0, float* __restrict__ C1, float* __restrict__ C2,
    int M, int N, int K, int lda, int ldb, int ldc)
{
    constexpr int KT  = 32;
    constexpr int SA  = KT + 4;                  /* 36  */
    constexpr int SBk = 128 + 8;                 /* 136 */
    constexpr int A_ELE = BM * SA;
    constexpr int B_ELE = KT * SBk;
    constexpr int STG = A_ELE + B_ELE;
    constexpr int AN = (BM == 128) ? 8 : 4;

    extern __shared__ float smem[];

    const int tid = threadIdx.x;
    const int lane = tid & 31, wid = tid >> 5;
    const int z = blockIdx.z;
    const float* B    = (z == 0) ? B0 : (z == 1) ? B1 : B2;
    const float* bias = (z == 0) ? bias0 : (z == 1) ? bias1 : bias2;
    float* C          = (z == 0) ? C0 : (z == 1) ? C1 : C2;

    const int bm = blockIdx.y * BM;
    const int bn = blockIdx.x * 128;
    const int mb = (BM == 128) ? (wid & 3) * 32 : (wid & 1) * 32;
    const int nb = (BM == 128) ? (wid >> 2) * 64 : (wid >> 1) * 32;

    float acc[2][AN][4];
    #pragma unroll
    for (int i = 0; i < 2; i++)
        #pragma unroll
        for (int j = 0; j < AN; j++)
            #pragma unroll
            for (int r = 0; r < 4; r++) acc[i][j][r] = 0.0f;

    auto issue = [&](int k0, int st) {
        float* As = smem + st * STG;
        float* Bs = As + A_ELE;
        #pragma unroll
        for (int i = 0; i < BM * KT / 1024; i++) {
            int f = tid + i * 256;
            int m = f >> 3, k4 = (f & 7) * 4;
            cp16(&As[m * SA + k4], &A[(size_t)(bm + m) * lda + k0 + k4]);
        }
        #pragma unroll
        for (int i = 0; i < 4; i++) {
            int f = tid + i * 256;
            int kk = f >> 5, n4 = (f & 31) * 4;
            cp16(&Bs[kk * SBk + n4], &B[(size_t)(k0 + kk) * ldb + bn + n4]);
        }
        asm volatile("cp.async.commit_group;" ::: "memory");
    };

    issue(0, 0);
    const int nIter = K / KT;
    for (int it = 0; it < nIter; it++) {
        if (it + 1 < nIter) {
            issue((it + 1) * KT, (it + 1) & 1);
            asm volatile("cp.async.wait_group 1;" ::: "memory");
        } else {
            asm volatile("cp.async.wait_group 0;" ::: "memory");
        }
        __syncthreads();

        float* As = smem + (it & 1) * STG;
        float* Bs = As + A_ELE;
        #pragma unroll
        for (int ks = 0; ks < KT / 8; ks++) {
            uint32_t af[2][4], bf[AN][2];
            #pragma unroll
            for (int am = 0; am < 2; am++)
                #pragma unroll
                for (int j = 0; j < 4; j++)
                    af[am][j] = f2tf(As[(mb + am * 16 + (lane >> 2) + (j & 1) * 8) * SA
                                        + ks * 8 + (lane & 3) + (j >> 1) * 4]);
            #pragma unroll
            for (int an = 0; an < AN; an++)
                #pragma unroll
                for (int j = 0; j < 2; j++)
                    bf[an][j] = f2tf(Bs[(ks * 8 + (lane & 3) + j * 4) * SBk
                                        + nb + an * 8 + (lane >> 2)]);
            #pragma unroll
            for (int am = 0; am < 2; am++)
                #pragma unroll
                for (int an = 0; an < AN; an++)
                    mma8(acc[am][an], af[am][0], af[am][1], af[am][2], af[am][3],
                         bf[an][0], bf[an][1]);
        }
        __syncthreads();
    }

    #pragma unroll
    for (int am = 0; am < 2; am++)
        #pragma unroll
        for (int an = 0; an < AN; an++)
            #pragma unroll
            for (int half = 0; half < 2; half++) {
                int m = bm + mb + am * 16 + (lane >> 2) + half * 8;
                int c = bn + nb + an * 8 + (lane & 3) * 2;
                float v0 = acc[am][an][half * 2 + 0] + bias[c];
                float v1 = acc[am][an][half * 2 + 1] + bias[c + 1];
                if (EPI == EPI_RELU) { v0 = fmaxf(v0, 0.0f); v1 = fmaxf(v1, 0.0f); }
                if (EPI == EPI_QKV) {
                    int bb = m >> 11, t = m & (T_SEQ - 1);
                    int h = c >> 6, d = c & (D_KK - 1);
                    *(float2*)&C[((size_t)((bb * N_HEADS + h) * T_SEQ) + t) * D_KK + d]
                        = make_float2(v0, v1);
                } else {
                    *(float2*)&C[(size_t)m * ldc + c] = make_float2(v0, v1);
                }
            }
}

/* ---------------- scores: attn <- exp2(QK^T * scale), partial row sums ----
 * tile 128(m) x 64(n), K=64 single shot. 3 CTAs/SM.
 */
__global__ __launch_bounds__(256, 3) void scores_kernel(
    const float* __restrict__ Q, const float* __restrict__ K,
    float* __restrict__ attn, float* __restrict__ psum)
{
    constexpr int S = 68;
    extern __shared__ float sm[];
    float* Qs = sm;              /* [128][68] */
    float* Ks = sm + 128 * S;    /* [64][68]  */

    const int tid = threadIdx.x;
    const int lane = tid & 31, wid = tid >> 5;
    const int z = blockIdx.z;
    const int bm = blockIdx.y * 128;
    const int bn = blockIdx.x * 64;
    Q += (size_t)z * T_SEQ * D_KK;
    K += (size_t)z * T_SEQ * D_KK;

    #pragma unroll
    for (int i = 0; i < 8; i++) {
        int f = tid + i * 256;
        int m = f >> 4, k4 = (f & 15) * 4;
        cp16(&Qs[m * S + k4], &Q[(size_t)(bm + m) * D_KK + k4]);
    }
    #pragma unroll
    for (int i = 0; i < 4; i++) {
        int f = tid + i * 256;
        int n = f >> 4, k4 = (f & 15) * 4;
        cp16(&Ks[n * S + k4], &K[(size_t)(bn + n) * D_KK + k4]);
    }
    asm volatile("cp.async.commit_group;" ::: "memory");
    asm volatile("cp.async.wait_group 0;" ::: "memory");
    __syncthreads();

    const int mb = (wid & 3) * 32;
    const int nwarp = wid >> 2;
    const int nb = nwarp * 32;

    float acc[2][4][4];
    #pragma unroll
    for (int i = 0; i < 2; i++)
        #pragma unroll
        for (int j = 0; j < 4; j++)
            #pragma unroll
            for (int r = 0; r < 4; r++) acc[i][j][r] = 0.0f;

    #pragma unroll
    for (int ks = 0; ks < 8; ks++) {
        uint32_t af[2][4], bf[4][2];
        #pragma unroll
        for (int am = 0; am < 2; am++)
            #pragma unroll
            for (int j = 0; j < 4; j++)
                af[am][j] = f2tf(Qs[(mb + am * 16 + (lane >> 2) + (j & 1) * 8) * S
                                    + ks * 8 + (lane & 3) + (j >> 1) * 4]);
        #pragma unroll
        for (int an = 0; an < 4; an++)
            #pragma unroll
            for (int j = 0; j < 2; j++)
                bf[an][j] = f2tf(Ks[(nb + an * 8 + (lane >> 2)) * S
                                    + ks * 8 + (lane & 3) + j * 4]);
        #pragma unroll
        for (int am = 0; am < 2; am++)
            #pragma unroll
            for (int an = 0; an < 4; an++)
                mma8(acc[am][an], af[am][0], af[am][1], af[am][2], af[am][3],
                     bf[an][0], bf[an][1]);
    }

    const float sc = 0.125f * LOG2E;
    float* Cz = attn + (size_t)z * T_SEQ * T_SEQ;
    #pragma unroll
    for (int am = 0; am < 2; am++)
        #pragma unroll
        for (int half = 0; half < 2; half++) {
            int m = bm + mb + am * 16 + (lane >> 2) + half * 8;
            float rs = 0.0f;
            #pragma unroll
            for (int an = 0; an < 4; an++) {
                int c = bn + nb + an * 8 + (lane & 3) * 2;
                float e0 = exp2f(acc[am][an][half * 2 + 0] * sc);
                float e1 = exp2f(acc[am][an][half * 2 + 1] * sc);
                *(float2*)&Cz[(size_t)m * T_SEQ + c] = make_float2(e0, e1);
                rs += e0 + e1;
            }
            rs += __shfl_xor_sync(0xffffffffu, rs, 1);
            rs += __shfl_xor_sync(0xffffffffu, rs, 2);
            if ((lane & 3) == 0)
                psum[((size_t)z * T_SEQ + m) * 64 + blockIdx.x * 2 + nwarp] = rs;
        }
}

/* ---------------- rowsum reduce + invert --------------------------------- */
__global__ __launch_bounds__(128) void rowsum_inv_kernel(
    const float* __restrict__ psum, float* __restrict__ inv)
{
    int r = blockIdx.x * 128 + threadIdx.x;
    const float4* p = (const float4*)(psum + (size_t)r * 64);
    float s = 0.0f;
    #pragma unroll
    for (int i = 0; i < 16; i++) {
        float4 v = p[i];
        s += v.x + v.y + v.z + v.w;
    }
    inv[r] = 1.0f / s;
}

/* ---------------- fused normalize + attn write + P@V ---------------------
 * cp.async double-buffered KT=64; normalization folded into A fragments and
 * the in-place attn write. */
__global__ __launch_bounds__(256) void attn_pv_kernel(
    float* __restrict__ attn, const float* __restrict__ V,
    const float* __restrict__ inv, float* __restrict__ ctx)
{
    constexpr int KT = 64;
    constexpr int SA = 68;     /* [m=128][k=64]+4 */
    constexpr int SV = 72;     /* [k=64][n=64]+8  */
    constexpr int A_ELE = 128 * SA;            /* 8704 */
    constexpr int STG = A_ELE + KT * SV;       /* 13312 */
    extern __shared__ float sm[];
    float* invs = sm + 2 * STG;

    const int tid = threadIdx.x;
    const int lane = tid & 31, wid = tid >> 5;
    const int bm = blockIdx.x * 128;
    const int z = blockIdx.y;
    attn += (size_t)z * T_SEQ * T_SEQ;
    V    += (size_t)z * T_SEQ * D_KK;

    if (tid < 128) invs[tid] = inv[(size_t)z * T_SEQ + bm + tid];

    auto issue = [&](int k0, int st) {
        float* As = sm + st * STG;
        float* Vs = As + A_ELE;
        #pragma unroll
        for (int i = 0; i < 8; i++) {
            int f = tid + i * 256;
            int m = f >> 4, k4 = (f & 15) * 4;
            cp16(&As[m * SA + k4], &attn[(size_t)(bm + m) * T_SEQ + k0 + k4]);
        }
        #pragma unroll
        for (int i = 0; i < 4; i++) {
            int f = tid + i * 256;
            int kk = f >> 4, c4 = (f & 15) * 4;
            cp16(&Vs[kk * SV + c4], &V[(size_t)(k0 + kk) * D_KK + c4]);
        }
        asm volatile("cp.async.commit_group;" ::: "memory");
    };

    issue(0, 0);
    const int mb = wid * 16;
    float acc[8][4];
    #pragma unroll
    for (int j = 0; j < 8; j++)
        #pragma unroll
        for (int r = 0; r < 4; r++) acc[j][r] = 0.0f;

    const int nIter = T_SEQ / KT;   /* 32 */
    for (int it = 0; it < nIter; it++) {
        if (it + 1 < nIter) {
            issue((it + 1) * KT, (it + 1) & 1);
            asm volatile("cp.async.wait_group 1;" ::: "memory");
        } else {
            asm volatile("cp.async.wait_group 0;" ::: "memory");
        }
        __syncthreads();

        float* As = sm + (it & 1) * STG;
        float* Vs = As + A_ELE;
        const float inv0 = invs[mb + (lane >> 2)];
        const float inv1 = invs[mb + (lane >> 2) + 8];

        #pragma unroll
        for (int ks = 0; ks < KT / 8; ks++) {
            uint32_t af[4], bf[8][2];
            #pragma unroll
            for (int j = 0; j < 4; j++) {
                float raw = As[(mb + (lane >> 2) + (j & 1) * 8) * SA
                               + ks * 8 + (lane & 3) + (j >> 1) * 4];
                af[j] = f2tf(raw * ((j & 1) ? inv1 : inv0));
            }
            #pragma unroll
            for (int an = 0; an < 8; an++)
                #pragma unroll
                for (int j = 0; j < 2; j++)
                    bf[an][j] = f2tf(Vs[(ks * 8 + (lane & 3) + j * 4) * SV
                                        + an * 8 + (lane >> 2)]);
            #pragma unroll
            for (int an = 0; an < 8; an++)
                mma8(acc[an], af[0], af[1], af[2], af[3], bf[an][0], bf[an][1]);
        }

        /* normalized in-place attn write from smem (coalesced STG.128) */
        #pragma unroll
        for (int i = 0; i < 8; i++) {
            int f = tid + i * 256;
            int m = f >> 4, k4 = (f & 15) * 4;
            float4 v = *(const float4*)&As[m * SA + k4];
            float iv = invs[m];
            v.x *= iv; v.y *= iv; v.z *= iv; v.w *= iv;
            *(float4*)&attn[(size_t)(bm + m) * T_SEQ + it * KT + k4] = v;
        }
        __syncthreads();
    }

    const int b = z >> 3, h = z & 7;
    float* Cz = ctx + (size_t)b * T_SEQ * D_MODEL + h * D_KK;
    #pragma unroll
    for (int an = 0; an < 8; an++)
        #pragma unroll
        for (int half = 0; half < 2; half++) {
            int m = bm + mb + (lane >> 2) + half * 8;
            int c = an * 8 + (lane & 3) * 2;
            *(float2*)&Cz[(size_t)m * D_MODEL + c]
                = make_float2(acc[an][half * 2 + 0], acc[an][half * 2 + 1]);
        }
}

/* ---------------- fused residual add + LayerNorm ------------------------- */
__global__ __launch_bounds__(128) void add_ln_kernel(
    const float* __restrict__ X, const float* __restrict__ Y,
    const float* __restrict__ g, const float* __restrict__ b,
    float* __restrict__ O)
{
    const int tid = threadIdx.x;
    const size_t base = (size_t)blockIdx.x * D_MODEL + tid * 4;
    float4 xv = *(const float4*)&X[base];
    float4 yv = *(const float4*)&Y[base];
    float4 v = make_float4(xv.x + yv.x, xv.y + yv.y, xv.z + yv.z, xv.w + yv.w);

    float s  = v.x + v.y + v.z + v.w;
    float ss = v.x * v.x + v.y * v.y + v.z * v.z + v.w * v.w;
    s = warp_sum(s);
    ss = warp_sum(ss);

    __shared__ float r1[4], r2[4];
    const int wid = tid >> 5, lane = tid & 31;
    if (lane == 0) { r1[wid] = s; r2[wid] = ss; }
    __syncthreads();
    if (tid == 0) {
        float a = 0.0f, c = 0.0f;
        #pragma unroll
        for (int i = 0; i < 4; i++) { a += r1[i]; c += r2[i]; }
        r1[0] = a; r2[0] = c;
    }
    __syncthreads();
    const float mu  = r1[0] * (1.0f / 512.0f);
    const float var = r2[0] * (1.0f / 512.0f) - mu * mu;
    const float rs  = rsqrtf(var + 1e-5f);

    float4 gv = *(const float4*)&g[tid * 4];
    float4 bv = *(const float4*)&b[tid * 4];
    float4 o;
    o.x = (v.x - mu) * rs * gv.x + bv.x;
    o.y = (v.y - mu) * rs * gv.y + bv.y;
    o.z = (v.z - mu) * rs * gv.z + bv.z;
    o.w = (v.w - mu) * rs * gv.w + bv.w;
    *(float4*)&O[base] = o;
}

/* ---------------- launch -------------------------------------------------- */
#define SMEM_G128   71680   /* 2*(128*36 + 32*136)*4 */
#define SMEM_G64    53248   /* 2*( 64*36 + 32*136)*4 */
#define SMEM_SCORES 52224   /* (128+64)*68*4 */
#define SMEM_PV     107008  /* (2*13312 + 128)*4 */

extern "C" void kernel_launch(void* const* d_in, const int* in_sizes, int n_in,
                              void* d_out, int out_size)
{
    const float* x     = (const float*)d_in[0];
    const float* wq_w  = (const float*)d_in[1];
    const float* wq_b  = (const float*)d_in[2];
    const float* wk_w  = (const float*)d_in[3];
    const float* wk_b  = (const float*)d_in[4];
    const float* wv_w  = (const float*)d_in[5];
    const float* wv_b  = (const float*)d_in[6];
    const float* wo_w  = (const float*)d_in[7];
    const float* wo_b  = (const float*)d_in[8];
    const float* ln1_g = (const float*)d_in[9];
    const float* ln1_b = (const float*)d_in[10];
    const float* fc1_w = (const float*)d_in[11];
    const float* fc1_b = (const float*)d_in[12];
    const float* fc2_w = (const float*)d_in[13];
    const float* fc2_b = (const float*)d_in[14];
    const float* ln2_g = (const float*)d_in[15];
    const float* ln2_b = (const float*)d_in[16];

    float* out = (float*)d_out;

    float *pq, *pk, *pv, *pctx, *ptmp, *ph, *pffn1, *ppsum, *pinv;
    cudaGetSymbolAddress((void**)&pq,    g_q);
    cudaGetSymbolAddress((void**)&pk,    g_k);
    cudaGetSymbolAddress((void**)&pv,    g_v);
    cudaGetSymbolAddress((void**)&pctx,  g_ctx);
    cudaGetSymbolAddress((void**)&ptmp,  g_tmp);
    cudaGetSymbolAddress((void**)&ph,    g_h);
    cudaGetSymbolAddress((void**)&pffn1, g_ffn1);
    cudaGetSymbolAddress((void**)&ppsum, g_psum);
    cudaGetSymbolAddress((void**)&pinv,  g_invsum);

    float* attn;
    if ((size_t)out_size >= OUT_ELEMS + ATTN_ELEMS) {
        attn = out + OUT_ELEMS;
    } else {
        cudaGetSymbolAddress((void**)&attn, g_attn_scratch);
    }

    cudaFuncSetAttribute(mma_gemm<128, EPI_QKV>,
                         cudaFuncAttributeMaxDynamicSharedMemorySize, SMEM_G128);
    cudaFuncSetAttribute(mma_gemm<128, EPI_BIAS>,
                         cudaFuncAttributeMaxDynamicSharedMemorySize, SMEM_G128);
    cudaFuncSetAttribute(mma_gemm<128, EPI_RELU>,
                         cudaFuncAttributeMaxDynamicSharedMemorySize, SMEM_G128);
    cudaFuncSetAttribute(mma_gemm<64, EPI_BIAS>,
                         cudaFuncAttributeMaxDynamicSharedMemorySize, SMEM_G64);
    cudaFuncSetAttribute(scores_kernel,
                         cudaFuncAttributeMaxDynamicSharedMemorySize, SMEM_SCORES);
    cudaFuncSetAttribute(attn_pv_kernel,
                         cudaFuncAttributeMaxDynamicSharedMemorySize, SMEM_PV);

    /* QKV: one launch, z selects weight/bias/output */
    mma_gemm<128, EPI_QKV><<<dim3(4, 32, 3), 256, SMEM_G128>>>(
        x, wq_w, wk_w, wv_w, wq_b, wk_b, wv_b, pq, pk, pv,
        BT, D_MODEL, D_MODEL, D_MODEL, D_MODEL, D_MODEL);

    /* scores + exp + partial row sums */
    scores_kernel<<<dim3(32, 16, BH), 256, SMEM_SCORES>>>(pq, pk, attn, ppsum);

    rowsum_inv_kernel<<<(BH * T_SEQ) / 128, 128>>>(ppsum, pinv);

    /* normalize attn in place + ctx = P @ V */
    attn_pv_kernel<<<dim3(T_SEQ / 128, BH), 256, SMEM_PV>>>(attn, pv, pinv, pctx);

    /* output projection + LN1 */
    mma_gemm<128, EPI_BIAS><<<dim3(4, 32, 1), 256, SMEM_G128>>>(
        pctx, wo_w, wo_w, wo_w, wo_b, wo_b, wo_b, ptmp, ptmp, ptmp,
        BT, D_MODEL, D_MODEL, D_MODEL, D_MODEL, D_MODEL);
    add_ln_kernel<<<BT, 128>>>(x, ptmp, ln1_g, ln1_b, ph);

    /* FFN + LN2 */
    mma_gemm<128, EPI_RELU><<<dim3(16, 32, 1), 256, SMEM_G128>>>(
        ph, fc1_w, fc1_w, fc1_w, fc1_b, fc1_b, fc1_b, pffn1, pffn1, pffn1,
        BT, D_FF, D_MODEL, D_MODEL, D_FF, D_FF);
    mma_gemm<64, EPI_BIAS><<<dim3(4, 64, 1), 256, SMEM_G64>>>(
        pffn1, fc2_w, fc2_w, fc2_w, fc2_b, fc2_b, fc2_b, ptmp, ptmp, ptmp,
        BT, D_MODEL, D_FF, D_FF, D_MODEL, D_MODEL);
    add_ln_kernel<<<BT, 128>>>(ph, ptmp, ln2_g, ln2_b, out);
}

// round 5
// speedup vs baseline: 3.5184x; 1.0605x over previous
#include <cuda_runtime.h>
#include <math.h>
#include <stdint.h>

#define D_MODEL 512
#define N_HEADS 8
#define D_KK    64
#define D_FF    2048
#define T_SEQ   2048
#define B_BATCH 2
#define BT      (B_BATCH * T_SEQ)
#define BH      (B_BATCH * N_HEADS)

#define OUT_ELEMS  ((size_t)BT * D_MODEL)
#define ATTN_ELEMS ((size_t)BH * T_SEQ * T_SEQ)

#define EPI_BIAS   0
#define EPI_RELU   1
#define EPI_QKV    2

#define LOG2E 1.4426950408889634f

/* ---------------- scratch ------------------------------------------------- */
__device__ float g_q[BH * T_SEQ * D_KK];
__device__ float g_k[BH * T_SEQ * D_KK];
__device__ float g_v[BH * T_SEQ * D_KK];
__device__ float g_ctx[BT * D_MODEL];
__device__ float g_tmp[BT * D_MODEL];
__device__ float g_h[BT * D_MODEL];
__device__ float g_ffn1[BT * D_FF];
__device__ float g_psum[(size_t)BH * T_SEQ * 64];
__device__ float g_invsum[(size_t)BH * T_SEQ];
__device__ float g_attn_scratch[BH * (size_t)T_SEQ * T_SEQ];

/* ---------------- helpers ------------------------------------------------- */
/* tf32 operand: HMMA reads top bits only; raw fp32 bits = RZ-truncated tf32.
 * Skips the cvt.rna ALU op entirely. */
__device__ __forceinline__ uint32_t f2tf(float f) { return __float_as_uint(f); }

__device__ __forceinline__ void mma8(float c[4], uint32_t a0, uint32_t a1,
                                     uint32_t a2, uint32_t a3,
                                     uint32_t b0, uint32_t b1) {
    asm volatile(
        "mma.sync.aligned.m16n8k8.row.col.f32.tf32.tf32.f32 "
        "{%0,%1,%2,%3}, {%4,%5,%6,%7}, {%8,%9}, {%0,%1,%2,%3};"
        : "+f"(c[0]), "+f"(c[1]), "+f"(c[2]), "+f"(c[3])
        : "r"(a0), "r"(a1), "r"(a2), "r"(a3), "r"(b0), "r"(b1));
}
__device__ __forceinline__ void cp16(float* sdst, const float* gsrc) {
    uint32_t s = (uint32_t)__cvta_generic_to_shared(sdst);
    asm volatile("cp.async.cg.shared.global [%0], [%1], 16;" :: "r"(s), "l"(gsrc));
}
__device__ __forceinline__ float warp_sum(float v) {
    #pragma unroll
    for (int o = 16; o > 0; o >>= 1) v += __shfl_xor_sync(0xffffffffu, v, o);
    return v;
}

/* ---------------- cp.async double-buffered tf32 GEMM --------------------- */
template <int BM, int EPI>
__global__ __launch_bounds__(256) void mma_gemm(
    const float* __restrict__ A,
    const float* __restrict__ B0, const float* __restrict__ B1, const float* __restrict__ B2,
    const float* __restrict__ bias0, const float* __restrict__ bias1, const float* __restrict__ bias2,
    float* __restrict__ C0, float* __restrict__ C1, float* __restrict__ C2,
    int M, int N, int K, int lda, int ldb, int ldc)
{
    constexpr int KT  = 32;
    constexpr int SA  = KT + 4;                  /* 36  */
    constexpr int SBk = 128 + 8;                 /* 136 */
    constexpr int A_ELE = BM * SA;
    constexpr int B_ELE = KT * SBk;
    constexpr int STG = A_ELE + B_ELE;
    constexpr int AN = (BM == 128) ? 8 : 4;

    extern __shared__ float smem[];

    const int tid = threadIdx.x;
    const int lane = tid & 31, wid = tid >> 5;
    const int z = blockIdx.z;
    const float* B    = (z == 0) ? B0 : (z == 1) ? B1 : B2;
    const float* bias = (z == 0) ? bias0 : (z == 1) ? bias1 : bias2;
    float* C          = (z == 0) ? C0 : (z == 1) ? C1 : C2;

    const int bm = blockIdx.y * BM;
    const int bn = blockIdx.x * 128;
    const int mb = (BM == 128) ? (wid & 3) * 32 : (wid & 1) * 32;
    const int nb = (BM == 128) ? (wid >> 2) * 64 : (wid >> 1) * 32;

    float acc[2][AN][4];
    #pragma unroll
    for (int i = 0; i < 2; i++)
        #pragma unroll
        for (int j = 0; j < AN; j++)
            #pragma unroll
            for (int r = 0; r < 4; r++) acc[i][j][r] = 0.0f;

    auto issue = [&](int k0, int st) {
        float* As = smem + st * STG;
        float* Bs = As + A_ELE;
        #pragma unroll
        for (int i = 0; i < BM * KT / 1024; i++) {
            int f = tid + i * 256;
            int m = f >> 3, k4 = (f & 7) * 4;
            cp16(&As[m * SA + k4], &A[(size_t)(bm + m) * lda + k0 + k4]);
        }
        #pragma unroll
        for (int i = 0; i < 4; i++) {
            int f = tid + i * 256;
            int kk = f >> 5, n4 = (f & 31) * 4;
            cp16(&Bs[kk * SBk + n4], &B[(size_t)(k0 + kk) * ldb + bn + n4]);
        }
        asm volatile("cp.async.commit_group;" ::: "memory");
    };

    issue(0, 0);
    const int nIter = K / KT;
    for (int it = 0; it < nIter; it++) {
        if (it + 1 < nIter) {
            issue((it + 1) * KT, (it + 1) & 1);
            asm volatile("cp.async.wait_group 1;" ::: "memory");
        } else {
            asm volatile("cp.async.wait_group 0;" ::: "memory");
        }
        __syncthreads();

        float* As = smem + (it & 1) * STG;
        float* Bs = As + A_ELE;
        #pragma unroll
        for (int ks = 0; ks < KT / 8; ks++) {
            uint32_t af[2][4], bf[AN][2];
            #pragma unroll
            for (int am = 0; am < 2; am++)
                #pragma unroll
                for (int j = 0; j < 4; j++)
                    af[am][j] = f2tf(As[(mb + am * 16 + (lane >> 2) + (j & 1) * 8) * SA
                                        + ks * 8 + (lane & 3) + (j >> 1) * 4]);
            #pragma unroll
            for (int an = 0; an < AN; an++)
                #pragma unroll
                for (int j = 0; j < 2; j++)
                    bf[an][j] = f2tf(Bs[(ks * 8 + (lane & 3) + j * 4) * SBk
                                        + nb + an * 8 + (lane >> 2)]);
            #pragma unroll
            for (int am = 0; am < 2; am++)
                #pragma unroll
                for (int an = 0; an < AN; an++)
                    mma8(acc[am][an], af[am][0], af[am][1], af[am][2], af[am][3],
                         bf[an][0], bf[an][1]);
        }
        __syncthreads();
    }

    #pragma unroll
    for (int am = 0; am < 2; am++)
        #pragma unroll
        for (int an = 0; an < AN; an++)
            #pragma unroll
            for (int half = 0; half < 2; half++) {
                int m = bm + mb + am * 16 + (lane >> 2) + half * 8;
                int c = bn + nb + an * 8 + (lane & 3) * 2;
                float v0 = acc[am][an][half * 2 + 0] + bias[c];
                float v1 = acc[am][an][half * 2 + 1] + bias[c + 1];
                if (EPI == EPI_RELU) { v0 = fmaxf(v0, 0.0f); v1 = fmaxf(v1, 0.0f); }
                if (EPI == EPI_QKV) {
                    int bb = m >> 11, t = m & (T_SEQ - 1);
                    int h = c >> 6, d = c & (D_KK - 1);
                    *(float2*)&C[((size_t)((bb * N_HEADS + h) * T_SEQ) + t) * D_KK + d]
                        = make_float2(v0, v1);
                } else {
                    *(float2*)&C[(size_t)m * ldc + c] = make_float2(v0, v1);
                }
            }
}

/* ---------------- scores: attn <- exp2(QK^T * scale), partial row sums ---- */
__global__ __launch_bounds__(256, 3) void scores_kernel(
    const float* __restrict__ Q, const float* __restrict__ K,
    float* __restrict__ attn, float* __restrict__ psum)
{
    constexpr int S = 68;
    extern __shared__ float sm[];
    float* Qs = sm;              /* [128][68] */
    float* Ks = sm + 128 * S;    /* [64][68]  */

    const int tid = threadIdx.x;
    const int lane = tid & 31, wid = tid >> 5;
    const int z = blockIdx.z;
    const int bm = blockIdx.y * 128;
    const int bn = blockIdx.x * 64;
    Q += (size_t)z * T_SEQ * D_KK;
    K += (size_t)z * T_SEQ * D_KK;

    #pragma unroll
    for (int i = 0; i < 8; i++) {
        int f = tid + i * 256;
        int m = f >> 4, k4 = (f & 15) * 4;
        cp16(&Qs[m * S + k4], &Q[(size_t)(bm + m) * D_KK + k4]);
    }
    #pragma unroll
    for (int i = 0; i < 4; i++) {
        int f = tid + i * 256;
        int n = f >> 4, k4 = (f & 15) * 4;
        cp16(&Ks[n * S + k4], &K[(size_t)(bn + n) * D_KK + k4]);
    }
    asm volatile("cp.async.commit_group;" ::: "memory");
    asm volatile("cp.async.wait_group 0;" ::: "memory");
    __syncthreads();

    const int mb = (wid & 3) * 32;
    const int nwarp = wid >> 2;
    const int nb = nwarp * 32;

    float acc[2][4][4];
    #pragma unroll
    for (int i = 0; i < 2; i++)
        #pragma unroll
        for (int j = 0; j < 4; j++)
            #pragma unroll
            for (int r = 0; r < 4; r++) acc[i][j][r] = 0.0f;

    #pragma unroll
    for (int ks = 0; ks < 8; ks++) {
        uint32_t af[2][4], bf[4][2];
        #pragma unroll
        for (int am = 0; am < 2; am++)
            #pragma unroll
            for (int j = 0; j < 4; j++)
                af[am][j] = f2tf(Qs[(mb + am * 16 + (lane >> 2) + (j & 1) * 8) * S
                                    + ks * 8 + (lane & 3) + (j >> 1) * 4]);
        #pragma unroll
        for (int an = 0; an < 4; an++)
            #pragma unroll
            for (int j = 0; j < 2; j++)
                bf[an][j] = f2tf(Ks[(nb + an * 8 + (lane >> 2)) * S
                                    + ks * 8 + (lane & 3) + j * 4]);
        #pragma unroll
        for (int am = 0; am < 2; am++)
            #pragma unroll
            for (int an = 0; an < 4; an++)
                mma8(acc[am][an], af[am][0], af[am][1], af[am][2], af[am][3],
                     bf[an][0], bf[an][1]);
    }

    const float sc = 0.125f * LOG2E;
    float* Cz = attn + (size_t)z * T_SEQ * T_SEQ;
    #pragma unroll
    for (int am = 0; am < 2; am++)
        #pragma unroll
        for (int half = 0; half < 2; half++) {
            int m = bm + mb + am * 16 + (lane >> 2) + half * 8;
            float rs = 0.0f;
            #pragma unroll
            for (int an = 0; an < 4; an++) {
                int c = bn + nb + an * 8 + (lane & 3) * 2;
                float e0 = exp2f(acc[am][an][half * 2 + 0] * sc);
                float e1 = exp2f(acc[am][an][half * 2 + 1] * sc);
                *(float2*)&Cz[(size_t)m * T_SEQ + c] = make_float2(e0, e1);
                rs += e0 + e1;
            }
            rs += __shfl_xor_sync(0xffffffffu, rs, 1);
            rs += __shfl_xor_sync(0xffffffffu, rs, 2);
            if ((lane & 3) == 0)
                psum[((size_t)z * T_SEQ + m) * 64 + blockIdx.x * 2 + nwarp] = rs;
        }
}

/* ---------------- rowsum reduce + invert --------------------------------- */
__global__ __launch_bounds__(128) void rowsum_inv_kernel(
    const float* __restrict__ psum, float* __restrict__ inv)
{
    int r = blockIdx.x * 128 + threadIdx.x;
    const float4* p = (const float4*)(psum + (size_t)r * 64);
    float s = 0.0f;
    #pragma unroll
    for (int i = 0; i < 16; i++) {
        float4 v = p[i];
        s += v.x + v.y + v.z + v.w;
    }
    inv[r] = 1.0f / s;
}

/* ---------------- fused normalize + attn write + P@V ---------------------
 * BM=64 tile (grid 512, 3 CTAs/SM). inv applied at ctx epilogue and attn
 * write only (row scaling commutes with P@V). KT=64 cp.async double buffer.
 */
__global__ __launch_bounds__(256, 3) void attn_pv_kernel(
    float* __restrict__ attn, const float* __restrict__ V,
    const float* __restrict__ inv, float* __restrict__ ctx)
{
    constexpr int KT = 64;
    constexpr int BM = 64;
    constexpr int SA = 68;     /* [m=64][k=64]+4 */
    constexpr int SV = 72;     /* [k=64][n=64]+8 */
    constexpr int A_ELE = BM * SA;             /* 4352 */
    constexpr int STG = A_ELE + KT * SV;       /* 8960 */
    extern __shared__ float sm[];
    float* invs = sm + 2 * STG;

    const int tid = threadIdx.x;
    const int lane = tid & 31, wid = tid >> 5;
    const int bm = blockIdx.x * BM;
    const int z = blockIdx.y;
    attn += (size_t)z * T_SEQ * T_SEQ;
    V    += (size_t)z * T_SEQ * D_KK;

    if (tid < BM) invs[tid] = inv[(size_t)z * T_SEQ + bm + tid];

    auto issue = [&](int k0, int st) {
        float* As = sm + st * STG;
        float* Vs = As + A_ELE;
        #pragma unroll
        for (int i = 0; i < 4; i++) {
            int f = tid + i * 256;
            int m = f >> 4, k4 = (f & 15) * 4;
            cp16(&As[m * SA + k4], &attn[(size_t)(bm + m) * T_SEQ + k0 + k4]);
        }
        #pragma unroll
        for (int i = 0; i < 4; i++) {
            int f = tid + i * 256;
            int kk = f >> 4, c4 = (f & 15) * 4;
            cp16(&Vs[kk * SV + c4], &V[(size_t)(k0 + kk) * D_KK + c4]);
        }
        asm volatile("cp.async.commit_group;" ::: "memory");
    };

    issue(0, 0);
    /* warp tile 32(m) x 16(n): mb = (wid&1)*32, nb = (wid>>1)*16 */
    const int mb = (wid & 1) * 32;
    const int nb = (wid >> 1) * 16;

    float acc[2][2][4];
    #pragma unroll
    for (int i = 0; i < 2; i++)
        #pragma unroll
        for (int j = 0; j < 2; j++)
            #pragma unroll
            for (int r = 0; r < 4; r++) acc[i][j][r] = 0.0f;

    const int nIter = T_SEQ / KT;   /* 32 */
    for (int it = 0; it < nIter; it++) {
        if (it + 1 < nIter) {
            issue((it + 1) * KT, (it + 1) & 1);
            asm volatile("cp.async.wait_group 1;" ::: "memory");
        } else {
            asm volatile("cp.async.wait_group 0;" ::: "memory");
        }
        __syncthreads();

        float* As = sm + (it & 1) * STG;
        float* Vs = As + A_ELE;

        #pragma unroll
        for (int ks = 0; ks < KT / 8; ks++) {
            uint32_t af[2][4], bf[2][2];
            #pragma unroll
            for (int am = 0; am < 2; am++)
                #pragma unroll
                for (int j = 0; j < 4; j++)
                    af[am][j] = f2tf(As[(mb + am * 16 + (lane >> 2) + (j & 1) * 8) * SA
                                        + ks * 8 + (lane & 3) + (j >> 1) * 4]);
            #pragma unroll
            for (int an = 0; an < 2; an++)
                #pragma unroll
                for (int j = 0; j < 2; j++)
                    bf[an][j] = f2tf(Vs[(ks * 8 + (lane & 3) + j * 4) * SV
                                        + nb + an * 8 + (lane >> 2)]);
            #pragma unroll
            for (int am = 0; am < 2; am++)
                #pragma unroll
                for (int an = 0; an < 2; an++)
                    mma8(acc[am][an], af[am][0], af[am][1], af[am][2], af[am][3],
                         bf[an][0], bf[an][1]);
        }

        /* normalized in-place attn write from smem (coalesced STG.128) */
        #pragma unroll
        for (int i = 0; i < 4; i++) {
            int f = tid + i * 256;
            int m = f >> 4, k4 = (f & 15) * 4;
            float4 v = *(const float4*)&As[m * SA + k4];
            float iv = invs[m];
            v.x *= iv; v.y *= iv; v.z *= iv; v.w *= iv;
            *(float4*)&attn[(size_t)(bm + m) * T_SEQ + it * KT + k4] = v;
        }
        __syncthreads();
    }

    const int b = z >> 3, h = z & 7;
    float* Cz = ctx + (size_t)b * T_SEQ * D_MODEL + h * D_KK;
    #pragma unroll
    for (int am = 0; am < 2; am++)
        #pragma unroll
        for (int an = 0; an < 2; an++)
            #pragma unroll
            for (int half = 0; half < 2; half++) {
                int mr = mb + am * 16 + (lane >> 2) + half * 8;
                int c = nb + an * 8 + (lane & 3) * 2;
                float iv = invs[mr];
                *(float2*)&Cz[(size_t)(bm + mr) * D_MODEL + c]
                    = make_float2(acc[am][an][half * 2 + 0] * iv,
                                  acc[am][an][half * 2 + 1] * iv);
            }
}

/* ---------------- fused residual add + LayerNorm ------------------------- */
__global__ __launch_bounds__(128) void add_ln_kernel(
    const float* __restrict__ X, const float* __restrict__ Y,
    const float* __restrict__ g, const float* __restrict__ b,
    float* __restrict__ O)
{
    const int tid = threadIdx.x;
    const size_t base = (size_t)blockIdx.x * D_MODEL + tid * 4;
    float4 xv = *(const float4*)&X[base];
    float4 yv = *(const float4*)&Y[base];
    float4 v = make_float4(xv.x + yv.x, xv.y + yv.y, xv.z + yv.z, xv.w + yv.w);

    float s  = v.x + v.y + v.z + v.w;
    float ss = v.x * v.x + v.y * v.y + v.z * v.z + v.w * v.w;
    s = warp_sum(s);
    ss = warp_sum(ss);

    __shared__ float r1[4], r2[4];
    const int wid = tid >> 5, lane = tid & 31;
    if (lane == 0) { r1[wid] = s; r2[wid] = ss; }
    __syncthreads();
    if (tid == 0) {
        float a = 0.0f, c = 0.0f;
        #pragma unroll
        for (int i = 0; i < 4; i++) { a += r1[i]; c += r2[i]; }
        r1[0] = a; r2[0] = c;
    }
    __syncthreads();
    const float mu  = r1[0] * (1.0f / 512.0f);
    const float var = r2[0] * (1.0f / 512.0f) - mu * mu;
    const float rs  = rsqrtf(var + 1e-5f);

    float4 gv = *(const float4*)&g[tid * 4];
    float4 bv = *(const float4*)&b[tid * 4];
    float4 o;
    o.x = (v.x - mu) * rs * gv.x + bv.x;
    o.y = (v.y - mu) * rs * gv.y + bv.y;
    o.z = (v.z - mu) * rs * gv.z + bv.z;
    o.w = (v.w - mu) * rs * gv.w + bv.w;
    *(float4*)&O[base] = o;
}

/* ---------------- launch -------------------------------------------------- */
#define SMEM_G128   71680   /* 2*(128*36 + 32*136)*4 */
#define SMEM_G64    53248   /* 2*( 64*36 + 32*136)*4 */
#define SMEM_SCORES 52224   /* (128+64)*68*4 */
#define SMEM_PV     71936   /* (2*8960 + 64)*4 */

extern "C" void kernel_launch(void* const* d_in, const int* in_sizes, int n_in,
                              void* d_out, int out_size)
{
    const float* x     = (const float*)d_in[0];
    const float* wq_w  = (const float*)d_in[1];
    const float* wq_b  = (const float*)d_in[2];
    const float* wk_w  = (const float*)d_in[3];
    const float* wk_b  = (const float*)d_in[4];
    const float* wv_w  = (const float*)d_in[5];
    const float* wv_b  = (const float*)d_in[6];
    const float* wo_w  = (const float*)d_in[7];
    const float* wo_b  = (const float*)d_in[8];
    const float* ln1_g = (const float*)d_in[9];
    const float* ln1_b = (const float*)d_in[10];
    const float* fc1_w = (const float*)d_in[11];
    const float* fc1_b = (const float*)d_in[12];
    const float* fc2_w = (const float*)d_in[13];
    const float* fc2_b = (const float*)d_in[14];
    const float* ln2_g = (const float*)d_in[15];
    const float* ln2_b = (const float*)d_in[16];

    float* out = (float*)d_out;

    float *pq, *pk, *pv, *pctx, *ptmp, *ph, *pffn1, *ppsum, *pinv;
    cudaGetSymbolAddress((void**)&pq,    g_q);
    cudaGetSymbolAddress((void**)&pk,    g_k);
    cudaGetSymbolAddress((void**)&pv,    g_v);
    cudaGetSymbolAddress((void**)&pctx,  g_ctx);
    cudaGetSymbolAddress((void**)&ptmp,  g_tmp);
    cudaGetSymbolAddress((void**)&ph,    g_h);
    cudaGetSymbolAddress((void**)&pffn1, g_ffn1);
    cudaGetSymbolAddress((void**)&ppsum, g_psum);
    cudaGetSymbolAddress((void**)&pinv,  g_invsum);

    float* attn;
    if ((size_t)out_size >= OUT_ELEMS + ATTN_ELEMS) {
        attn = out + OUT_ELEMS;
    } else {
        cudaGetSymbolAddress((void**)&attn, g_attn_scratch);
    }

    cudaFuncSetAttribute(mma_gemm<128, EPI_QKV>,
                         cudaFuncAttributeMaxDynamicSharedMemorySize, SMEM_G128);
    cudaFuncSetAttribute(mma_gemm<128, EPI_BIAS>,
                         cudaFuncAttributeMaxDynamicSharedMemorySize, SMEM_G128);
    cudaFuncSetAttribute(mma_gemm<128, EPI_RELU>,
                         cudaFuncAttributeMaxDynamicSharedMemorySize, SMEM_G128);
    cudaFuncSetAttribute(mma_gemm<64, EPI_BIAS>,
                         cudaFuncAttributeMaxDynamicSharedMemorySize, SMEM_G64);
    cudaFuncSetAttribute(scores_kernel,
                         cudaFuncAttributeMaxDynamicSharedMemorySize, SMEM_SCORES);
    cudaFuncSetAttribute(attn_pv_kernel,
                         cudaFuncAttributeMaxDynamicSharedMemorySize, SMEM_PV);

    /* QKV: one launch, z selects weight/bias/output */
    mma_gemm<128, EPI_QKV><<<dim3(4, 32, 3), 256, SMEM_G128>>>(
        x, wq_w, wk_w, wv_w, wq_b, wk_b, wv_b, pq, pk, pv,
        BT, D_MODEL, D_MODEL, D_MODEL, D_MODEL, D_MODEL);

    /* scores + exp + partial row sums */
    scores_kernel<<<dim3(32, 16, BH), 256, SMEM_SCORES>>>(pq, pk, attn, ppsum);

    rowsum_inv_kernel<<<(BH * T_SEQ) / 128, 128>>>(ppsum, pinv);

    /* normalize attn in place + ctx = P @ V (inv folded into epilogues) */
    attn_pv_kernel<<<dim3(T_SEQ / 64, BH), 256, SMEM_PV>>>(attn, pv, pinv, pctx);

    /* output projection + LN1 */
    mma_gemm<128, EPI_BIAS><<<dim3(4, 32, 1), 256, SMEM_G128>>>(
        pctx, wo_w, wo_w, wo_w, wo_b, wo_b, wo_b, ptmp, ptmp, ptmp,
        BT, D_MODEL, D_MODEL, D_MODEL, D_MODEL, D_MODEL);
    add_ln_kernel<<<BT, 128>>>(x, ptmp, ln1_g, ln1_b, ph);

    /* FFN + LN2 */
    mma_gemm<128, EPI_RELU><<<dim3(16, 32, 1), 256, SMEM_G128>>>(
        ph, fc1_w, fc1_w, fc1_w, fc1_b, fc1_b, fc1_b, pffn1, pffn1, pffn1,
        BT, D_FF, D_MODEL, D_MODEL, D_FF, D_FF);
    mma_gemm<64, EPI_BIAS><<<dim3(4, 64, 1), 256, SMEM_G64>>>(
        pffn1, fc2_w, fc2_w, fc2_w, fc2_b, fc2_b, fc2_b, ptmp, ptmp, ptmp,
        BT, D_MODEL, D_FF, D_FF, D_MODEL, D_MODEL);
    add_ln_kernel<<<BT, 128>>>(ph, ptmp, ln2_g, ln2_b, out);
}